// round 13
// baseline (speedup 1.0000x reference)
#include <cuda_runtime.h>
#include <math_constants.h>

#define BB 8
#define NN 2048
#define KNN 20
#define NTOT (BB*NN)
#define EPSB 1e-5f
#define FULLM 0xFFFFFFFFu
#define ENC_NEGINF 0x007FFFFFu   // fenc(-INF)

// ---------------- scratch (device globals; no allocation allowed) ----------
__device__ int      g_idx[NTOT*KNN];
__device__ float    g_x1[NTOT*64];
__device__ float    g_x2[NTOT*64];
__device__ float    g_x3[NTOT*64];
__device__ float    g_Y[NTOT*64];
__device__ float    g_T[NTOT*64];
__device__ float4   g_pts[NTOT];
__device__ unsigned g_gmax[BB*1024];

__device__ __forceinline__ float lrelu(float z){ return z >= 0.f ? z : 0.2f*z; }
__device__ __forceinline__ unsigned fenc(float f){
    unsigned u = __float_as_uint(f);
    return u ^ ((unsigned)((int)u >> 31) | 0x80000000u);
}
__device__ __forceinline__ unsigned fencs(float f){
    unsigned u = __float_as_uint(f);
    return (u & 0x80000000u) ? ~u : (u | 0x80000000u);
}
__device__ __forceinline__ float fdec(unsigned e){
    return (e & 0x80000000u) ? __uint_as_float(e ^ 0x80000000u) : __uint_as_float(~e);
}

// ---------------- packed f32x2 helpers (FFMA2 — PTX-only pattern) ----------
__device__ __forceinline__ unsigned long long pack2(float v){
    unsigned long long r;
    asm("mov.b64 %0, {%1, %1};" : "=l"(r) : "f"(v));
    return r;
}
__device__ __forceinline__ void fma2(unsigned long long& d,
                                     unsigned long long a, unsigned long long b){
    asm("fma.rn.f32x2 %0, %1, %2, %0;" : "+l"(d) : "l"(a), "l"(b));
}
__device__ __forceinline__ float2 unpack2(unsigned long long v){
    float lo, hi;
    asm("mov.b64 {%0, %1}, %2;" : "=f"(lo), "=f"(hi) : "l"(v));
    return make_float2(lo, hi);
}

// ---------------- prep (stage 1 only): pack x as float4 (x,y,z,|p|^2) ------
__global__ __launch_bounds__(256) void prep_pts_kernel(const float* __restrict__ x)
{
    int t = blockIdx.x*256 + threadIdx.x;
    if (t >= NTOT) return;
    const float* src = x + (size_t)t*3;
    float px = src[0], py = src[1], pz = src[2];
    g_pts[t] = make_float4(px, py, pz, px*px + py*py + pz*pz);
}

// ---------------- kNN v7: warp-per-query, enc-domain + redux inserts -------
__global__ __launch_bounds__(256) void knn_kernel()
{
    __shared__ float4 pts[NN];
    int tid = threadIdx.x;
    int b = blockIdx.x;
    for (int j = tid; j < NN; j += 256)
        pts[j] = g_pts[(size_t)b*NN + j];
    __syncthreads();

    int w = tid >> 5, lane = tid & 31;
    int i = blockIdx.y*8 + w;
    float4 q = pts[i];
    float qx2 = 2.f*q.x, qy2 = 2.f*q.y, qz2 = 2.f*q.z, qw = q.w;

    unsigned be  = (lane < KNN) ? ENC_NEGINF : 0xFFFFFFFFu;
    int      bi  = 0;
    unsigned thr = ENC_NEGINF;

    for (int ch = 0; ch < NN/64; ch++){
        int j0 = ch*64 + lane;
        float4 p0 = pts[j0];
        float4 p1 = pts[j0 + 32];
        float t0 = fmaf(qz2, p0.z, -qw);
        t0 = fmaf(qy2, p0.y, t0);
        t0 = fmaf(qx2, p0.x, t0);
        unsigned e0 = fenc(t0 - p0.w);
        float t1 = fmaf(qz2, p1.z, -qw);
        t1 = fmaf(qy2, p1.y, t1);
        t1 = fmaf(qx2, p1.x, t1);
        unsigned e1 = fenc(t1 - p1.w);

        unsigned mask = __ballot_sync(FULLM, e0 > thr);
        while (mask){
            int src = __ffs(mask) - 1;
            mask &= mask - 1;
            unsigned e = __shfl_sync(FULLM, e0, src);
            if (e > thr){
                unsigned mv = __reduce_min_sync(FULLM, be);
                if (e > mv){
                    unsigned own = __ballot_sync(FULLM, be == mv);
                    int ml = __ffs(own) - 1;
                    if (lane == ml){ be = e; bi = j0 - lane + src; }
                }
                thr = mv;
            }
        }
        mask = __ballot_sync(FULLM, e1 > thr);
        while (mask){
            int src = __ffs(mask) - 1;
            mask &= mask - 1;
            unsigned e = __shfl_sync(FULLM, e1, src);
            if (e > thr){
                unsigned mv = __reduce_min_sync(FULLM, be);
                if (e > mv){
                    unsigned own = __ballot_sync(FULLM, be == mv);
                    int ml = __ffs(own) - 1;
                    if (lane == ml){ be = e; bi = j0 - lane + 32 + src; }
                }
                thr = mv;
            }
        }
    }
    if (lane < KNN)
        g_idx[((size_t)b*NN + i)*KNN + lane] = bi;
}

// ---------------- gemmYT v2: Y' = s*(x@Wlo^T), T' = s*(x@Wd^T)+b -----------
template<int C, int SEL>
__global__ __launch_bounds__(256) void gemmYT_kernel(
    const float* __restrict__ x, const float* __restrict__ W,
    const float* __restrict__ bng, const float* __restrict__ bnb,
    const float* __restrict__ bnm, const float* __restrict__ bnv)
{
    const float* __restrict__ xin = (SEL == 0) ? x : (SEL == 1) ? g_x1 : g_x2;

    __shared__ __align__(16) float Wlo[C*64];
    __shared__ __align__(16) float Wd [C*64];
    __shared__ __align__(16) float xS [32*C];

    int tid = threadIdx.x;
    int pt0 = blockIdx.x*32;

    for (int t = tid; t < C*64; t += 256){
        int o = t & 63, c = t >> 6;
        float lo = W[(size_t)o*(2*C) + c];
        Wlo[c*64 + o] = lo;
        Wd [c*64 + o] = W[(size_t)o*(2*C) + C + c] - lo;
    }
    for (int t = tid; t < 32*C; t += 256){
        int p = t / C, c = t % C;
        xS[p*C + c] = xin[((size_t)pt0 + p)*C + c];
    }
    __syncthreads();

    int o0 = (tid & 15)*4;
    int p0 = (tid >> 4)*2, p1 = p0 + 1;

    float aY0[4]={0,0,0,0}, aT0[4]={0,0,0,0};
    float aY1[4]={0,0,0,0}, aT1[4]={0,0,0,0};

#pragma unroll 4
    for (int c = 0; c < C; c++){
        float4 wl = *(const float4*)&Wlo[c*64 + o0];
        float4 wd = *(const float4*)&Wd [c*64 + o0];
        float x0 = xS[p0*C + c];
        float x1 = xS[p1*C + c];
        aY0[0]=fmaf(x0,wl.x,aY0[0]); aY0[1]=fmaf(x0,wl.y,aY0[1]);
        aY0[2]=fmaf(x0,wl.z,aY0[2]); aY0[3]=fmaf(x0,wl.w,aY0[3]);
        aT0[0]=fmaf(x0,wd.x,aT0[0]); aT0[1]=fmaf(x0,wd.y,aT0[1]);
        aT0[2]=fmaf(x0,wd.z,aT0[2]); aT0[3]=fmaf(x0,wd.w,aT0[3]);
        aY1[0]=fmaf(x1,wl.x,aY1[0]); aY1[1]=fmaf(x1,wl.y,aY1[1]);
        aY1[2]=fmaf(x1,wl.z,aY1[2]); aY1[3]=fmaf(x1,wl.w,aY1[3]);
        aT1[0]=fmaf(x1,wd.x,aT1[0]); aT1[1]=fmaf(x1,wd.y,aT1[1]);
        aT1[2]=fmaf(x1,wd.z,aT1[2]); aT1[3]=fmaf(x1,wd.w,aT1[3]);
    }

    float4 gv = *(const float4*)&bng[o0];
    float4 bv = *(const float4*)&bnb[o0];
    float4 mv = *(const float4*)&bnm[o0];
    float4 vv = *(const float4*)&bnv[o0];
    float s[4], bo[4];
    s[0] = gv.x*rsqrtf(vv.x + EPSB); bo[0] = bv.x - mv.x*s[0];
    s[1] = gv.y*rsqrtf(vv.y + EPSB); bo[1] = bv.y - mv.y*s[1];
    s[2] = gv.z*rsqrtf(vv.z + EPSB); bo[2] = bv.z - mv.z*s[2];
    s[3] = gv.w*rsqrtf(vv.w + EPSB); bo[3] = bv.w - mv.w*s[3];

    float4 r;
    r = make_float4(s[0]*aY0[0], s[1]*aY0[1], s[2]*aY0[2], s[3]*aY0[3]);
    *(float4*)&g_Y[((size_t)pt0 + p0)*64 + o0] = r;
    r = make_float4(s[0]*aY1[0], s[1]*aY1[1], s[2]*aY1[2], s[3]*aY1[3]);
    *(float4*)&g_Y[((size_t)pt0 + p1)*64 + o0] = r;
    r = make_float4(fmaf(s[0],aT0[0],bo[0]), fmaf(s[1],aT0[1],bo[1]),
                    fmaf(s[2],aT0[2],bo[2]), fmaf(s[3],aT0[3],bo[3]));
    *(float4*)&g_T[((size_t)pt0 + p0)*64 + o0] = r;
    r = make_float4(fmaf(s[0],aT1[0],bo[0]), fmaf(s[1],aT1[1],bo[1]),
                    fmaf(s[2],aT1[2],bo[2]), fmaf(s[3],aT1[3],bo[3]));
    *(float4*)&g_T[((size_t)pt0 + p1)*64 + o0] = r;
}

// ---------------- edge_conv2 v3: FFMA2 inner loop, 5x8 tile ----------------
template<int SEL_OUT>
__global__ __launch_bounds__(256) void edge_conv2_kernel(
    const float* __restrict__ Wb,
    const float* __restrict__ bng, const float* __restrict__ bnb,
    const float* __restrict__ bnm, const float* __restrict__ bnv)
{
    float* __restrict__ xout = (SEL_OUT == 1) ? g_x1 : g_x2;

    __shared__ __align__(16) float Ws[64*64];
    __shared__ __align__(16) float As[64*161];
    __shared__ __align__(16) float red[4*8*64];
    __shared__ int idxS[160];

    int tid = threadIdx.x;
    int pt0 = blockIdx.x*8;

    for (int t = tid; t < 4096; t += 256){
        int o = t & 63, c = t >> 6;
        Ws[c*64 + o] = Wb[(size_t)o*64 + c];
    }
    if (tid < 160) idxS[tid] = g_idx[(size_t)pt0*KNN + tid];
    __syncthreads();

    for (int e = tid; e < 160*64; e += 256){
        int r = e >> 6, c = e & 63;
        int p = r / KNN;
        int bb = (pt0 + p) >> 11;
        int j = idxS[r];
        float v = g_Y[((size_t)bb*NN + j)*64 + c] + g_T[((size_t)pt0 + p)*64 + c];
        As[c*161 + r] = lrelu(v);
    }

    int r5 = tid & 31;
    int og = (tid >> 5) * 8;

    float s2[8], b2[8];
#pragma unroll
    for (int q = 0; q < 8; q++){
        int o = og + q;
        float r = rsqrtf(bnv[o] + EPSB);
        s2[q] = bng[o]*r; b2[q] = bnb[o] - bnm[o]*s2[q];
    }
    __syncthreads();

    unsigned long long acc2[5][4];   // [row][output-pair], packed f32x2
#pragma unroll
    for (int i = 0; i < 5; i++)
#pragma unroll
        for (int q = 0; q < 4; q++) acc2[i][q] = 0ULL;

#pragma unroll 4
    for (int c = 0; c < 64; c++){
        ulonglong2 w01 = *(const ulonglong2*)&Ws[c*64 + og];      // outputs (0,1),(2,3)
        ulonglong2 w23 = *(const ulonglong2*)&Ws[c*64 + og + 4];  // outputs (4,5),(6,7)
        float a[5];
#pragma unroll
        for (int i = 0; i < 5; i++) a[i] = As[c*161 + r5*5 + i];
#pragma unroll
        for (int i = 0; i < 5; i++){
            unsigned long long ap = pack2(a[i]);
            fma2(acc2[i][0], ap, w01.x);
            fma2(acc2[i][1], ap, w01.y);
            fma2(acc2[i][2], ap, w23.x);
            fma2(acc2[i][3], ap, w23.y);
        }
    }

    int p    = r5 >> 2;
    int part = r5 & 3;
#pragma unroll
    for (int qp = 0; qp < 4; qp++){
        float mxl = -CUDART_INF_F, mxh = -CUDART_INF_F;
#pragma unroll
        for (int i = 0; i < 5; i++){
            float2 v = unpack2(acc2[i][qp]);
            mxl = fmaxf(mxl, lrelu(fmaf(v.x, s2[2*qp],   b2[2*qp])));
            mxh = fmaxf(mxh, lrelu(fmaf(v.y, s2[2*qp+1], b2[2*qp+1])));
        }
        red[(part*8 + p)*64 + og + 2*qp]     = mxl;
        red[(part*8 + p)*64 + og + 2*qp + 1] = mxh;
    }
    __syncthreads();

    for (int t = tid; t < 512; t += 256){
        int pp = t >> 6, oo = t & 63;
        float m = red[(0*8 + pp)*64 + oo];
        m = fmaxf(m, red[(1*8 + pp)*64 + oo]);
        m = fmaxf(m, red[(2*8 + pp)*64 + oo]);
        m = fmaxf(m, red[(3*8 + pp)*64 + oo]);
        xout[((size_t)pt0 + pp)*64 + oo] = m;
    }

    // fused prep for the NEXT stage's kNN: pts = (c6,c7,c8,|p|^2) from red[]
    if (tid < 8){
        int pp = tid;
        float v[3];
#pragma unroll
        for (int c = 0; c < 3; c++){
            float m = red[(0*8 + pp)*64 + 6 + c];
            m = fmaxf(m, red[(1*8 + pp)*64 + 6 + c]);
            m = fmaxf(m, red[(2*8 + pp)*64 + 6 + c]);
            m = fmaxf(m, red[(3*8 + pp)*64 + 6 + c]);
            v[c] = m;
        }
        g_pts[pt0 + pp] = make_float4(v[0], v[1], v[2],
                                      v[0]*v[0] + v[1]*v[1] + v[2]*v[2]);
    }
}

// ---------------- edge_max (stage 3): x3 = max_k lrelu(Y'[j]+T'[i]) --------
__global__ __launch_bounds__(256) void edge_max_kernel()
{
    __shared__ int idxS[4*KNN];
    int tid = threadIdx.x;
    int pt0 = blockIdx.x*4;
    if (tid < 4*KNN) idxS[tid] = g_idx[(size_t)pt0*KNN + tid];
    __syncthreads();

    int p = tid >> 6, o = tid & 63;
    int pt = pt0 + p;
    int bb = pt >> 11;
    float tv = g_T[(size_t)pt*64 + o];
    float m = -CUDART_INF_F;
#pragma unroll
    for (int k = 0; k < KNN; k++){
        int j = idxS[p*KNN + k];
        m = fmaxf(m, lrelu(g_Y[((size_t)bb*NN + j)*64 + o] + tv));
    }
    g_x3[(size_t)pt*64 + o] = m;
}

// ---------------- init / final GEMM v3 (FFMA2) / outputs -------------------
__global__ void init_gmax_kernel(){
    int t = blockIdx.x*256 + threadIdx.x;
    if (t < BB*1024) g_gmax[t] = 0u;
}

__global__ __launch_bounds__(256) void final_kernel(
    const float* __restrict__ W6,
    const float* __restrict__ bn6g, const float* __restrict__ bn6b,
    const float* __restrict__ bn6m, const float* __restrict__ bn6v)
{
    extern __shared__ float dsm[];
    float* Bs = dsm;              // [192*68]
    float* As = dsm + 192*68;     // [192*68]
    __shared__ float ss6[64], sb6[64];
    __shared__ float red[64*16];

    int tid = threadIdx.x;
    int n0 = blockIdx.x*64;
    int bb = blockIdx.y;
    int mc = blockIdx.z;

    if (tid < 64){
        int o = n0 + tid;
        float r = rsqrtf(bn6v[o] + EPSB);
        ss6[tid] = bn6g[o]*r; sb6[tid] = bn6b[o] - bn6m[o]*ss6[tid];
    }

    for (int ch = 0; ch < 3; ch++)
        for (int t = tid; t < 4096; t += 256){
            int nn = t >> 6, c = t & 63;
            Bs[(ch*64 + c)*68 + nn] = W6[(size_t)(n0+nn)*192 + ch*64 + c];
        }
    __syncthreads();

    int tm = tid & 15, tn = tid >> 4;
    float s6[4], b6[4];
#pragma unroll
    for (int q = 0; q < 4; q++){ s6[q] = ss6[tn*4+q]; b6[q] = sb6[tn*4+q]; }

    float vmax[4] = {-CUDART_INF_F, -CUDART_INF_F, -CUDART_INF_F, -CUDART_INF_F};

    for (int mi = mc*8; mi < mc*8 + 8; mi++){
        size_t m1 = (size_t)bb*NN + mi*64;
        __syncthreads();
        {
            for (int t = tid; t < 4096; t += 256){
                int m = t >> 6, c = t & 63;
                As[(0*64 + c)*68 + m] = g_x1[(m1 + m)*64 + c];
            }
            for (int t = tid; t < 4096; t += 256){
                int m = t >> 6, c = t & 63;
                As[(1*64 + c)*68 + m] = g_x2[(m1 + m)*64 + c];
            }
            for (int t = tid; t < 4096; t += 256){
                int m = t >> 6, c = t & 63;
                As[(2*64 + c)*68 + m] = g_x3[(m1 + m)*64 + c];
            }
        }
        __syncthreads();

        unsigned long long acc2[4][2];   // [m][n-pair]
#pragma unroll
        for (int i = 0; i < 4; i++){ acc2[i][0] = 0ULL; acc2[i][1] = 0ULL; }

#pragma unroll 8
        for (int c = 0; c < 192; c++){
            float4 a = *(const float4*)&As[c*68 + tm*4];
            ulonglong2 bp = *(const ulonglong2*)&Bs[c*68 + tn*4];
            unsigned long long a0 = pack2(a.x), a1 = pack2(a.y),
                               a2 = pack2(a.z), a3 = pack2(a.w);
            fma2(acc2[0][0], a0, bp.x); fma2(acc2[0][1], a0, bp.y);
            fma2(acc2[1][0], a1, bp.x); fma2(acc2[1][1], a1, bp.y);
            fma2(acc2[2][0], a2, bp.x); fma2(acc2[2][1], a2, bp.y);
            fma2(acc2[3][0], a3, bp.x); fma2(acc2[3][1], a3, bp.y);
        }
#pragma unroll
        for (int mq = 0; mq < 4; mq++){
            float2 v0 = unpack2(acc2[mq][0]);
            float2 v1 = unpack2(acc2[mq][1]);
            vmax[0] = fmaxf(vmax[0], lrelu(fmaf(v0.x, s6[0], b6[0])));
            vmax[1] = fmaxf(vmax[1], lrelu(fmaf(v0.y, s6[1], b6[1])));
            vmax[2] = fmaxf(vmax[2], lrelu(fmaf(v1.x, s6[2], b6[2])));
            vmax[3] = fmaxf(vmax[3], lrelu(fmaf(v1.y, s6[3], b6[3])));
        }
    }

    __syncthreads();
#pragma unroll
    for (int nq = 0; nq < 4; nq++) red[(tn*4+nq)*16 + tm] = vmax[nq];
    __syncthreads();
    if (tid < 64){
        float mx = -CUDART_INF_F;
#pragma unroll
        for (int t = 0; t < 16; t++) mx = fmaxf(mx, red[tid*16 + t]);
        atomicMax(&g_gmax[bb*1024 + n0 + tid], fencs(mx));
    }
}

__global__ void feat_kernel(float* __restrict__ out){
    int t = blockIdx.x*256 + threadIdx.x;
    if (t < BB*1024) out[t] = fdec(g_gmax[t]);
}

// ---------------- x4^T via smem transpose ----------------------------------
__global__ __launch_bounds__(256) void x4t_kernel(float* __restrict__ out)
{
    __shared__ float T[64*65];
    int tid = threadIdx.x;
    int n0 = blockIdx.x*64;
    int bb = blockIdx.y;
    int ch = blockIdx.z;
    const float* src = (ch == 0) ? g_x1 : (ch == 1) ? g_x2 : g_x3;

    for (int t = tid; t < 4096; t += 256){
        int c = t & 63, n = t >> 6;
        T[c*65 + n] = src[((size_t)bb*NN + n0 + n)*64 + c];
    }
    __syncthreads();
    size_t base = (size_t)BB*1024 + (size_t)bb*192*NN + (size_t)ch*64*NN;
    for (int t = tid; t < 4096; t += 256){
        int n = t & 63, c = t >> 6;
        out[base + (size_t)c*NN + n0 + n] = T[c*65 + n];
    }
}

// ---------------- launch: fork-join across two streams ---------------------
extern "C" void kernel_launch(void* const* d_in, const int* in_sizes, int n_in,
                              void* d_out, int out_size)
{
    const float* x    = (const float*)d_in[0];
    const float* W1   = (const float*)d_in[1];
    const float* W2   = (const float*)d_in[2];
    const float* W3   = (const float*)d_in[3];
    const float* W4   = (const float*)d_in[4];
    const float* W5   = (const float*)d_in[5];
    const float* W6   = (const float*)d_in[6];
    const float* bng  = (const float*)d_in[7];
    const float* bnb  = (const float*)d_in[8];
    const float* bnm  = (const float*)d_in[9];
    const float* bnv  = (const float*)d_in[10];
    const float* bn6g = (const float*)d_in[11];
    const float* bn6b = (const float*)d_in[12];
    const float* bn6m = (const float*)d_in[13];
    const float* bn6v = (const float*)d_in[14];
    float* out = (float*)d_out;

    static cudaStream_t s1 = nullptr;
    static cudaEvent_t evF, evB, evX1, evC, evX2, evE, evM, evJ;
    if (!s1){
        cudaStreamCreateWithFlags(&s1, cudaStreamNonBlocking);
        cudaEventCreateWithFlags(&evF,  cudaEventDisableTiming);
        cudaEventCreateWithFlags(&evB,  cudaEventDisableTiming);
        cudaEventCreateWithFlags(&evX1, cudaEventDisableTiming);
        cudaEventCreateWithFlags(&evC,  cudaEventDisableTiming);
        cudaEventCreateWithFlags(&evX2, cudaEventDisableTiming);
        cudaEventCreateWithFlags(&evE,  cudaEventDisableTiming);
        cudaEventCreateWithFlags(&evM,  cudaEventDisableTiming);
        cudaEventCreateWithFlags(&evJ,  cudaEventDisableTiming);
        cudaFuncSetAttribute(final_kernel,
            cudaFuncAttributeMaxDynamicSharedMemorySize, 2*192*68*4);
    }
    const int FSMEM = 2*192*68*4;

    // ---- Stage 1 ----                               (kernel launch order)
    prep_pts_kernel<<<NTOT/256, 256>>>(x);                              // 0
    cudaEventRecord(evF, 0);
    cudaStreamWaitEvent(s1, evF, 0);
    gemmYT_kernel<3,0><<<NTOT/32, 256, 0, s1>>>(x, W1, bng, bnb, bnm, bnv); // 1
    cudaEventRecord(evB, s1);
    knn_kernel<<<dim3(BB, NN/8), 256>>>();                              // 2
    cudaStreamWaitEvent(0, evB, 0);
    edge_conv2_kernel<1><<<NTOT/8, 256>>>(W2, bng+64, bnb+64, bnm+64, bnv+64); // 3 <- ncu
    cudaEventRecord(evX1, 0);
    init_gmax_kernel<<<32, 256>>>();                                    // 4 (s0)

    // ---- Stage 2 ----  gemmYT on s1 overlaps knn on s0
    cudaStreamWaitEvent(s1, evX1, 0);
    gemmYT_kernel<64,1><<<NTOT/32, 256, 0, s1>>>(x, W3, bng+2*64, bnb+2*64, bnm+2*64, bnv+2*64);
    cudaEventRecord(evC, s1);
    knn_kernel<<<dim3(BB, NN/8), 256>>>();
    cudaStreamWaitEvent(0, evC, 0);
    edge_conv2_kernel<2><<<NTOT/8, 256>>>(W4, bng+3*64, bnb+3*64, bnm+3*64, bnv+3*64);
    cudaEventRecord(evX2, 0);

    // ---- Stage 3 ----
    cudaStreamWaitEvent(s1, evX2, 0);
    gemmYT_kernel<64,2><<<NTOT/32, 256, 0, s1>>>(x, W5, bng+4*64, bnb+4*64, bnm+4*64, bnv+4*64);
    cudaEventRecord(evE, s1);
    knn_kernel<<<dim3(BB, NN/8), 256>>>();
    cudaStreamWaitEvent(0, evE, 0);
    edge_max_kernel<<<NTOT/4, 256>>>();
    cudaEventRecord(evM, 0);

    // ---- Final: x4t (s1) overlaps final GEMM (s0) ----
    cudaStreamWaitEvent(s1, evM, 0);
    x4t_kernel<<<dim3(NN/64, BB, 3), 256, 0, s1>>>(out);
    cudaEventRecord(evJ, s1);
    final_kernel<<<dim3(1024/64, BB, 4), 256, FSMEM>>>(W6, bn6g, bn6b, bn6m, bn6v);
    feat_kernel<<<32, 256>>>(out);
    cudaStreamWaitEvent(0, evJ, 0);   // join s1 into s0 before capture ends
}

// round 14
// speedup vs baseline: 1.0364x; 1.0364x over previous
#include <cuda_runtime.h>
#include <math_constants.h>

#define BB 8
#define NN 2048
#define KNN 20
#define NTOT (BB*NN)
#define EPSB 1e-5f
#define FULLM 0xFFFFFFFFu
#define ENC_NEGINF 0x007FFFFFu   // fenc(-INF)

// ---------------- scratch (device globals; no allocation allowed) ----------
__device__ int      g_idx[NTOT*KNN];
__device__ float    g_x1[NTOT*64];
__device__ float    g_x2[NTOT*64];
__device__ float    g_x3[NTOT*64];
__device__ float    g_Y[NTOT*64];
__device__ float    g_T[NTOT*64];
__device__ float4   g_pts[NTOT];
__device__ unsigned g_gmax[BB*1024];

__device__ __forceinline__ float lrelu(float z){ return z >= 0.f ? z : 0.2f*z; }
__device__ __forceinline__ unsigned fenc(float f){
    unsigned u = __float_as_uint(f);
    return u ^ ((unsigned)((int)u >> 31) | 0x80000000u);
}
__device__ __forceinline__ unsigned fencs(float f){
    unsigned u = __float_as_uint(f);
    return (u & 0x80000000u) ? ~u : (u | 0x80000000u);
}
__device__ __forceinline__ float fdec(unsigned e){
    return (e & 0x80000000u) ? __uint_as_float(e ^ 0x80000000u) : __uint_as_float(~e);
}

// ---------------- packed f32x2 helpers (FFMA2 — used in final only) --------
__device__ __forceinline__ unsigned long long pack2(float v){
    unsigned long long r;
    asm("mov.b64 %0, {%1, %1};" : "=l"(r) : "f"(v));
    return r;
}
__device__ __forceinline__ void fma2(unsigned long long& d,
                                     unsigned long long a, unsigned long long b){
    asm("fma.rn.f32x2 %0, %1, %2, %0;" : "+l"(d) : "l"(a), "l"(b));
}
__device__ __forceinline__ float2 unpack2(unsigned long long v){
    float lo, hi;
    asm("mov.b64 {%0, %1}, %2;" : "=f"(lo), "=f"(hi) : "l"(v));
    return make_float2(lo, hi);
}

// ---------------- prep (stage 1 only): pack x as float4 (x,y,z,|p|^2) ------
__global__ __launch_bounds__(256) void prep_pts_kernel(const float* __restrict__ x)
{
    int t = blockIdx.x*256 + threadIdx.x;
    if (t >= NTOT) return;
    const float* src = x + (size_t)t*3;
    float px = src[0], py = src[1], pz = src[2];
    g_pts[t] = make_float4(px, py, pz, px*px + py*py + pz*pz);
}

// ---------------- kNN v7: warp-per-query, enc-domain + redux inserts -------
__global__ __launch_bounds__(256) void knn_kernel()
{
    __shared__ float4 pts[NN];
    int tid = threadIdx.x;
    int b = blockIdx.x;
    for (int j = tid; j < NN; j += 256)
        pts[j] = g_pts[(size_t)b*NN + j];
    __syncthreads();

    int w = tid >> 5, lane = tid & 31;
    int i = blockIdx.y*8 + w;
    float4 q = pts[i];
    float qx2 = 2.f*q.x, qy2 = 2.f*q.y, qz2 = 2.f*q.z, qw = q.w;

    unsigned be  = (lane < KNN) ? ENC_NEGINF : 0xFFFFFFFFu;
    int      bi  = 0;
    unsigned thr = ENC_NEGINF;

    for (int ch = 0; ch < NN/64; ch++){
        int j0 = ch*64 + lane;
        float4 p0 = pts[j0];
        float4 p1 = pts[j0 + 32];
        float t0 = fmaf(qz2, p0.z, -qw);
        t0 = fmaf(qy2, p0.y, t0);
        t0 = fmaf(qx2, p0.x, t0);
        unsigned e0 = fenc(t0 - p0.w);
        float t1 = fmaf(qz2, p1.z, -qw);
        t1 = fmaf(qy2, p1.y, t1);
        t1 = fmaf(qx2, p1.x, t1);
        unsigned e1 = fenc(t1 - p1.w);

        unsigned mask = __ballot_sync(FULLM, e0 > thr);
        while (mask){
            int src = __ffs(mask) - 1;
            mask &= mask - 1;
            unsigned e = __shfl_sync(FULLM, e0, src);
            if (e > thr){
                unsigned mv = __reduce_min_sync(FULLM, be);
                if (e > mv){
                    unsigned own = __ballot_sync(FULLM, be == mv);
                    int ml = __ffs(own) - 1;
                    if (lane == ml){ be = e; bi = j0 - lane + src; }
                }
                thr = mv;
            }
        }
        mask = __ballot_sync(FULLM, e1 > thr);
        while (mask){
            int src = __ffs(mask) - 1;
            mask &= mask - 1;
            unsigned e = __shfl_sync(FULLM, e1, src);
            if (e > thr){
                unsigned mv = __reduce_min_sync(FULLM, be);
                if (e > mv){
                    unsigned own = __ballot_sync(FULLM, be == mv);
                    int ml = __ffs(own) - 1;
                    if (lane == ml){ be = e; bi = j0 - lane + 32 + src; }
                }
                thr = mv;
            }
        }
    }
    if (lane < KNN)
        g_idx[((size_t)b*NN + i)*KNN + lane] = bi;
}

// ---------------- gemmYT v2: Y' = s*(x@Wlo^T), T' = s*(x@Wd^T)+b -----------
template<int C, int SEL>
__global__ __launch_bounds__(256) void gemmYT_kernel(
    const float* __restrict__ x, const float* __restrict__ W,
    const float* __restrict__ bng, const float* __restrict__ bnb,
    const float* __restrict__ bnm, const float* __restrict__ bnv)
{
    const float* __restrict__ xin = (SEL == 0) ? x : (SEL == 1) ? g_x1 : g_x2;

    __shared__ __align__(16) float Wlo[C*64];
    __shared__ __align__(16) float Wd [C*64];
    __shared__ __align__(16) float xS [32*C];

    int tid = threadIdx.x;
    int pt0 = blockIdx.x*32;

    for (int t = tid; t < C*64; t += 256){
        int o = t & 63, c = t >> 6;
        float lo = W[(size_t)o*(2*C) + c];
        Wlo[c*64 + o] = lo;
        Wd [c*64 + o] = W[(size_t)o*(2*C) + C + c] - lo;
    }
    for (int t = tid; t < 32*C; t += 256){
        int p = t / C, c = t % C;
        xS[p*C + c] = xin[((size_t)pt0 + p)*C + c];
    }
    __syncthreads();

    int o0 = (tid & 15)*4;
    int p0 = (tid >> 4)*2, p1 = p0 + 1;

    float aY0[4]={0,0,0,0}, aT0[4]={0,0,0,0};
    float aY1[4]={0,0,0,0}, aT1[4]={0,0,0,0};

#pragma unroll 4
    for (int c = 0; c < C; c++){
        float4 wl = *(const float4*)&Wlo[c*64 + o0];
        float4 wd = *(const float4*)&Wd [c*64 + o0];
        float x0 = xS[p0*C + c];
        float x1 = xS[p1*C + c];
        aY0[0]=fmaf(x0,wl.x,aY0[0]); aY0[1]=fmaf(x0,wl.y,aY0[1]);
        aY0[2]=fmaf(x0,wl.z,aY0[2]); aY0[3]=fmaf(x0,wl.w,aY0[3]);
        aT0[0]=fmaf(x0,wd.x,aT0[0]); aT0[1]=fmaf(x0,wd.y,aT0[1]);
        aT0[2]=fmaf(x0,wd.z,aT0[2]); aT0[3]=fmaf(x0,wd.w,aT0[3]);
        aY1[0]=fmaf(x1,wl.x,aY1[0]); aY1[1]=fmaf(x1,wl.y,aY1[1]);
        aY1[2]=fmaf(x1,wl.z,aY1[2]); aY1[3]=fmaf(x1,wl.w,aY1[3]);
        aT1[0]=fmaf(x1,wd.x,aT1[0]); aT1[1]=fmaf(x1,wd.y,aT1[1]);
        aT1[2]=fmaf(x1,wd.z,aT1[2]); aT1[3]=fmaf(x1,wd.w,aT1[3]);
    }

    float4 gv = *(const float4*)&bng[o0];
    float4 bv = *(const float4*)&bnb[o0];
    float4 mv = *(const float4*)&bnm[o0];
    float4 vv = *(const float4*)&bnv[o0];
    float s[4], bo[4];
    s[0] = gv.x*rsqrtf(vv.x + EPSB); bo[0] = bv.x - mv.x*s[0];
    s[1] = gv.y*rsqrtf(vv.y + EPSB); bo[1] = bv.y - mv.y*s[1];
    s[2] = gv.z*rsqrtf(vv.z + EPSB); bo[2] = bv.z - mv.z*s[2];
    s[3] = gv.w*rsqrtf(vv.w + EPSB); bo[3] = bv.w - mv.w*s[3];

    float4 r;
    r = make_float4(s[0]*aY0[0], s[1]*aY0[1], s[2]*aY0[2], s[3]*aY0[3]);
    *(float4*)&g_Y[((size_t)pt0 + p0)*64 + o0] = r;
    r = make_float4(s[0]*aY1[0], s[1]*aY1[1], s[2]*aY1[2], s[3]*aY1[3]);
    *(float4*)&g_Y[((size_t)pt0 + p1)*64 + o0] = r;
    r = make_float4(fmaf(s[0],aT0[0],bo[0]), fmaf(s[1],aT0[1],bo[1]),
                    fmaf(s[2],aT0[2],bo[2]), fmaf(s[3],aT0[3],bo[3]));
    *(float4*)&g_T[((size_t)pt0 + p0)*64 + o0] = r;
    r = make_float4(fmaf(s[0],aT1[0],bo[0]), fmaf(s[1],aT1[1],bo[1]),
                    fmaf(s[2],aT1[2],bo[2]), fmaf(s[3],aT1[3],bo[3]));
    *(float4*)&g_T[((size_t)pt0 + p1)*64 + o0] = r;
}

// ---------------- edge_conv2 v2 (scalar 5x8, restored): -> conv-b -> k-max -
template<int SEL_OUT>
__global__ __launch_bounds__(256) void edge_conv2_kernel(
    const float* __restrict__ Wb,
    const float* __restrict__ bng, const float* __restrict__ bnb,
    const float* __restrict__ bnm, const float* __restrict__ bnv)
{
    float* __restrict__ xout = (SEL_OUT == 1) ? g_x1 : g_x2;

    __shared__ __align__(16) float Ws[64*64];
    __shared__ __align__(16) float As[64*161];
    __shared__ __align__(16) float red[4*8*64];
    __shared__ int idxS[160];

    int tid = threadIdx.x;
    int pt0 = blockIdx.x*8;

    for (int t = tid; t < 4096; t += 256){
        int o = t & 63, c = t >> 6;
        Ws[c*64 + o] = Wb[(size_t)o*64 + c];
    }
    if (tid < 160) idxS[tid] = g_idx[(size_t)pt0*KNN + tid];
    __syncthreads();

    for (int e = tid; e < 160*64; e += 256){
        int r = e >> 6, c = e & 63;
        int p = r / KNN;
        int bb = (pt0 + p) >> 11;
        int j = idxS[r];
        float v = g_Y[((size_t)bb*NN + j)*64 + c] + g_T[((size_t)pt0 + p)*64 + c];
        As[c*161 + r] = lrelu(v);
    }

    int r5 = tid & 31;
    int og = (tid >> 5) * 8;

    float s2[8], b2[8];
#pragma unroll
    for (int q = 0; q < 8; q++){
        int o = og + q;
        float r = rsqrtf(bnv[o] + EPSB);
        s2[q] = bng[o]*r; b2[q] = bnb[o] - bnm[o]*s2[q];
    }
    __syncthreads();

    float acc[5][8];
#pragma unroll
    for (int i = 0; i < 5; i++)
#pragma unroll
        for (int q = 0; q < 8; q++) acc[i][q] = 0.f;

#pragma unroll 4
    for (int c = 0; c < 64; c++){
        float4 wA = *(const float4*)&Ws[c*64 + og];
        float4 wB = *(const float4*)&Ws[c*64 + og + 4];
        float a[5];
#pragma unroll
        for (int i = 0; i < 5; i++) a[i] = As[c*161 + r5*5 + i];
#pragma unroll
        for (int i = 0; i < 5; i++){
            acc[i][0]=fmaf(a[i],wA.x,acc[i][0]); acc[i][1]=fmaf(a[i],wA.y,acc[i][1]);
            acc[i][2]=fmaf(a[i],wA.z,acc[i][2]); acc[i][3]=fmaf(a[i],wA.w,acc[i][3]);
            acc[i][4]=fmaf(a[i],wB.x,acc[i][4]); acc[i][5]=fmaf(a[i],wB.y,acc[i][5]);
            acc[i][6]=fmaf(a[i],wB.z,acc[i][6]); acc[i][7]=fmaf(a[i],wB.w,acc[i][7]);
        }
    }

    int p    = r5 >> 2;
    int part = r5 & 3;
#pragma unroll
    for (int q = 0; q < 8; q++){
        float mx = -CUDART_INF_F;
#pragma unroll
        for (int i = 0; i < 5; i++)
            mx = fmaxf(mx, lrelu(fmaf(acc[i][q], s2[q], b2[q])));
        red[(part*8 + p)*64 + og + q] = mx;
    }
    __syncthreads();

    for (int t = tid; t < 512; t += 256){
        int pp = t >> 6, oo = t & 63;
        float m = red[(0*8 + pp)*64 + oo];
        m = fmaxf(m, red[(1*8 + pp)*64 + oo]);
        m = fmaxf(m, red[(2*8 + pp)*64 + oo]);
        m = fmaxf(m, red[(3*8 + pp)*64 + oo]);
        xout[((size_t)pt0 + pp)*64 + oo] = m;
    }

    // fused prep for the NEXT stage's kNN: pts = (c6,c7,c8,|p|^2) from red[]
    if (tid < 8){
        int pp = tid;
        float v[3];
#pragma unroll
        for (int c = 0; c < 3; c++){
            float m = red[(0*8 + pp)*64 + 6 + c];
            m = fmaxf(m, red[(1*8 + pp)*64 + 6 + c]);
            m = fmaxf(m, red[(2*8 + pp)*64 + 6 + c]);
            m = fmaxf(m, red[(3*8 + pp)*64 + 6 + c]);
            v[c] = m;
        }
        g_pts[pt0 + pp] = make_float4(v[0], v[1], v[2],
                                      v[0]*v[0] + v[1]*v[1] + v[2]*v[2]);
    }
}

// ---------------- edge_max (stage 3): x3 = max_k lrelu(Y'[j]+T'[i]) --------
__global__ __launch_bounds__(256) void edge_max_kernel()
{
    __shared__ int idxS[4*KNN];
    int tid = threadIdx.x;
    int pt0 = blockIdx.x*4;
    if (tid < 4*KNN) idxS[tid] = g_idx[(size_t)pt0*KNN + tid];
    __syncthreads();

    int p = tid >> 6, o = tid & 63;
    int pt = pt0 + p;
    int bb = pt >> 11;
    float tv = g_T[(size_t)pt*64 + o];
    float m = -CUDART_INF_F;
#pragma unroll
    for (int k = 0; k < KNN; k++){
        int j = idxS[p*KNN + k];
        m = fmaxf(m, lrelu(g_Y[((size_t)bb*NN + j)*64 + o] + tv));
    }
    g_x3[(size_t)pt*64 + o] = m;
}

// ---------------- init / final GEMM v3 (FFMA2, kept) / outputs -------------
__global__ void init_gmax_kernel(){
    int t = blockIdx.x*256 + threadIdx.x;
    if (t < BB*1024) g_gmax[t] = 0u;
}

__global__ __launch_bounds__(256) void final_kernel(
    const float* __restrict__ W6,
    const float* __restrict__ bn6g, const float* __restrict__ bn6b,
    const float* __restrict__ bn6m, const float* __restrict__ bn6v)
{
    extern __shared__ float dsm[];
    float* Bs = dsm;              // [192*68]
    float* As = dsm + 192*68;     // [192*68]
    __shared__ float ss6[64], sb6[64];
    __shared__ float red[64*16];

    int tid = threadIdx.x;
    int n0 = blockIdx.x*64;
    int bb = blockIdx.y;
    int mc = blockIdx.z;

    if (tid < 64){
        int o = n0 + tid;
        float r = rsqrtf(bn6v[o] + EPSB);
        ss6[tid] = bn6g[o]*r; sb6[tid] = bn6b[o] - bn6m[o]*ss6[tid];
    }

    for (int ch = 0; ch < 3; ch++)
        for (int t = tid; t < 4096; t += 256){
            int nn = t >> 6, c = t & 63;
            Bs[(ch*64 + c)*68 + nn] = W6[(size_t)(n0+nn)*192 + ch*64 + c];
        }
    __syncthreads();

    int tm = tid & 15, tn = tid >> 4;
    float s6[4], b6[4];
#pragma unroll
    for (int q = 0; q < 4; q++){ s6[q] = ss6[tn*4+q]; b6[q] = sb6[tn*4+q]; }

    float vmax[4] = {-CUDART_INF_F, -CUDART_INF_F, -CUDART_INF_F, -CUDART_INF_F};

    for (int mi = mc*8; mi < mc*8 + 8; mi++){
        size_t m1 = (size_t)bb*NN + mi*64;
        __syncthreads();
        {
            for (int t = tid; t < 4096; t += 256){
                int m = t >> 6, c = t & 63;
                As[(0*64 + c)*68 + m] = g_x1[(m1 + m)*64 + c];
            }
            for (int t = tid; t < 4096; t += 256){
                int m = t >> 6, c = t & 63;
                As[(1*64 + c)*68 + m] = g_x2[(m1 + m)*64 + c];
            }
            for (int t = tid; t < 4096; t += 256){
                int m = t >> 6, c = t & 63;
                As[(2*64 + c)*68 + m] = g_x3[(m1 + m)*64 + c];
            }
        }
        __syncthreads();

        unsigned long long acc2[4][2];   // [m][n-pair]
#pragma unroll
        for (int i = 0; i < 4; i++){ acc2[i][0] = 0ULL; acc2[i][1] = 0ULL; }

#pragma unroll 8
        for (int c = 0; c < 192; c++){
            float4 a = *(const float4*)&As[c*68 + tm*4];
            ulonglong2 bp = *(const ulonglong2*)&Bs[c*68 + tn*4];
            unsigned long long a0 = pack2(a.x), a1 = pack2(a.y),
                               a2 = pack2(a.z), a3 = pack2(a.w);
            fma2(acc2[0][0], a0, bp.x); fma2(acc2[0][1], a0, bp.y);
            fma2(acc2[1][0], a1, bp.x); fma2(acc2[1][1], a1, bp.y);
            fma2(acc2[2][0], a2, bp.x); fma2(acc2[2][1], a2, bp.y);
            fma2(acc2[3][0], a3, bp.x); fma2(acc2[3][1], a3, bp.y);
        }
#pragma unroll
        for (int mq = 0; mq < 4; mq++){
            float2 v0 = unpack2(acc2[mq][0]);
            float2 v1 = unpack2(acc2[mq][1]);
            vmax[0] = fmaxf(vmax[0], lrelu(fmaf(v0.x, s6[0], b6[0])));
            vmax[1] = fmaxf(vmax[1], lrelu(fmaf(v0.y, s6[1], b6[1])));
            vmax[2] = fmaxf(vmax[2], lrelu(fmaf(v1.x, s6[2], b6[2])));
            vmax[3] = fmaxf(vmax[3], lrelu(fmaf(v1.y, s6[3], b6[3])));
        }
    }

    __syncthreads();
#pragma unroll
    for (int nq = 0; nq < 4; nq++) red[(tn*4+nq)*16 + tm] = vmax[nq];
    __syncthreads();
    if (tid < 64){
        float mx = -CUDART_INF_F;
#pragma unroll
        for (int t = 0; t < 16; t++) mx = fmaxf(mx, red[tid*16 + t]);
        atomicMax(&g_gmax[bb*1024 + n0 + tid], fencs(mx));
    }
}

__global__ void feat_kernel(float* __restrict__ out){
    int t = blockIdx.x*256 + threadIdx.x;
    if (t < BB*1024) out[t] = fdec(g_gmax[t]);
}

// ---------------- x4^T via smem transpose ----------------------------------
__global__ __launch_bounds__(256) void x4t_kernel(float* __restrict__ out)
{
    __shared__ float T[64*65];
    int tid = threadIdx.x;
    int n0 = blockIdx.x*64;
    int bb = blockIdx.y;
    int ch = blockIdx.z;
    const float* src = (ch == 0) ? g_x1 : (ch == 1) ? g_x2 : g_x3;

    for (int t = tid; t < 4096; t += 256){
        int c = t & 63, n = t >> 6;
        T[c*65 + n] = src[((size_t)bb*NN + n0 + n)*64 + c];
    }
    __syncthreads();
    size_t base = (size_t)BB*1024 + (size_t)bb*192*NN + (size_t)ch*64*NN;
    for (int t = tid; t < 4096; t += 256){
        int n = t & 63, c = t >> 6;
        out[base + (size_t)c*NN + n0 + n] = T[c*65 + n];
    }
}

// ---------------- launch: fork-join across two streams ---------------------
extern "C" void kernel_launch(void* const* d_in, const int* in_sizes, int n_in,
                              void* d_out, int out_size)
{
    const float* x    = (const float*)d_in[0];
    const float* W1   = (const float*)d_in[1];
    const float* W2   = (const float*)d_in[2];
    const float* W3   = (const float*)d_in[3];
    const float* W4   = (const float*)d_in[4];
    const float* W5   = (const float*)d_in[5];
    const float* W6   = (const float*)d_in[6];
    const float* bng  = (const float*)d_in[7];
    const float* bnb  = (const float*)d_in[8];
    const float* bnm  = (const float*)d_in[9];
    const float* bnv  = (const float*)d_in[10];
    const float* bn6g = (const float*)d_in[11];
    const float* bn6b = (const float*)d_in[12];
    const float* bn6m = (const float*)d_in[13];
    const float* bn6v = (const float*)d_in[14];
    float* out = (float*)d_out;

    static cudaStream_t s1 = nullptr;
    static cudaEvent_t evF, evB, evX1, evC, evX2, evE, evM, evJ;
    if (!s1){
        cudaStreamCreateWithFlags(&s1, cudaStreamNonBlocking);
        cudaEventCreateWithFlags(&evF,  cudaEventDisableTiming);
        cudaEventCreateWithFlags(&evB,  cudaEventDisableTiming);
        cudaEventCreateWithFlags(&evX1, cudaEventDisableTiming);
        cudaEventCreateWithFlags(&evC,  cudaEventDisableTiming);
        cudaEventCreateWithFlags(&evX2, cudaEventDisableTiming);
        cudaEventCreateWithFlags(&evE,  cudaEventDisableTiming);
        cudaEventCreateWithFlags(&evM,  cudaEventDisableTiming);
        cudaEventCreateWithFlags(&evJ,  cudaEventDisableTiming);
        cudaFuncSetAttribute(final_kernel,
            cudaFuncAttributeMaxDynamicSharedMemorySize, 2*192*68*4);
    }
    const int FSMEM = 2*192*68*4;

    // ---- Stage 1 ----                               (kernel launch order)
    prep_pts_kernel<<<NTOT/256, 256>>>(x);                              // 0
    cudaEventRecord(evF, 0);
    cudaStreamWaitEvent(s1, evF, 0);
    gemmYT_kernel<3,0><<<NTOT/32, 256, 0, s1>>>(x, W1, bng, bnb, bnm, bnv); // 1
    cudaEventRecord(evB, s1);
    knn_kernel<<<dim3(BB, NN/8), 256>>>();                              // 2
    cudaStreamWaitEvent(0, evB, 0);
    edge_conv2_kernel<1><<<NTOT/8, 256>>>(W2, bng+64, bnb+64, bnm+64, bnv+64); // 3 <- ncu
    cudaEventRecord(evX1, 0);
    init_gmax_kernel<<<32, 256>>>();                                    // 4 (s0)

    // ---- Stage 2 ----  gemmYT on s1 overlaps knn on s0
    cudaStreamWaitEvent(s1, evX1, 0);
    gemmYT_kernel<64,1><<<NTOT/32, 256, 0, s1>>>(x, W3, bng+2*64, bnb+2*64, bnm+2*64, bnv+2*64);
    cudaEventRecord(evC, s1);
    knn_kernel<<<dim3(BB, NN/8), 256>>>();
    cudaStreamWaitEvent(0, evC, 0);
    edge_conv2_kernel<2><<<NTOT/8, 256>>>(W4, bng+3*64, bnb+3*64, bnm+3*64, bnv+3*64);
    cudaEventRecord(evX2, 0);

    // ---- Stage 3 ----
    cudaStreamWaitEvent(s1, evX2, 0);
    gemmYT_kernel<64,2><<<NTOT/32, 256, 0, s1>>>(x, W5, bng+4*64, bnb+4*64, bnm+4*64, bnv+4*64);
    cudaEventRecord(evE, s1);
    knn_kernel<<<dim3(BB, NN/8), 256>>>();
    cudaStreamWaitEvent(0, evE, 0);
    edge_max_kernel<<<NTOT/4, 256>>>();
    cudaEventRecord(evM, 0);

    // ---- Final: x4t (s1) overlaps final GEMM (s0) ----
    cudaStreamWaitEvent(s1, evM, 0);
    x4t_kernel<<<dim3(NN/64, BB, 3), 256, 0, s1>>>(out);
    cudaEventRecord(evJ, s1);
    final_kernel<<<dim3(1024/64, BB, 4), 256, FSMEM>>>(W6, bn6g, bn6b, bn6m, bn6v);
    feat_kernel<<<32, 256>>>(out);
    cudaStreamWaitEvent(0, evJ, 0);   // join s1 into s0 before capture ends
}

// round 15
// speedup vs baseline: 1.0745x; 1.0367x over previous
#include <cuda_runtime.h>
#include <math_constants.h>

#define BB 8
#define NB 4              // batches per pipeline (2 pipelines)
#define NN 2048
#define KNN 20
#define NTOT (BB*NN)
#define EPSB 1e-5f
#define FULLM 0xFFFFFFFFu
#define ENC_NEGINF 0x007FFFFFu   // fenc(-INF)

// ---------------- scratch (device globals; no allocation allowed) ----------
__device__ int      g_idx[NTOT*KNN];
__device__ float    g_x1[NTOT*64];
__device__ float    g_x2[NTOT*64];
__device__ float    g_x3[NTOT*64];
__device__ float    g_Y[NTOT*64];
__device__ float    g_T[NTOT*64];
__device__ float4   g_pts[NTOT];
__device__ unsigned g_gmax[BB*1024];

__device__ __forceinline__ float lrelu(float z){ return z >= 0.f ? z : 0.2f*z; }
__device__ __forceinline__ unsigned fenc(float f){
    unsigned u = __float_as_uint(f);
    return u ^ ((unsigned)((int)u >> 31) | 0x80000000u);
}
__device__ __forceinline__ unsigned fencs(float f){
    unsigned u = __float_as_uint(f);
    return (u & 0x80000000u) ? ~u : (u | 0x80000000u);
}
__device__ __forceinline__ float fdec(unsigned e){
    return (e & 0x80000000u) ? __uint_as_float(e ^ 0x80000000u) : __uint_as_float(~e);
}

// ---------------- packed f32x2 helpers (FFMA2 — used in final only) --------
__device__ __forceinline__ unsigned long long pack2(float v){
    unsigned long long r;
    asm("mov.b64 %0, {%1, %1};" : "=l"(r) : "f"(v));
    return r;
}
__device__ __forceinline__ void fma2(unsigned long long& d,
                                     unsigned long long a, unsigned long long b){
    asm("fma.rn.f32x2 %0, %1, %2, %0;" : "+l"(d) : "l"(a), "l"(b));
}
__device__ __forceinline__ float2 unpack2(unsigned long long v){
    float lo, hi;
    asm("mov.b64 {%0, %1}, %2;" : "=f"(lo), "=f"(hi) : "l"(v));
    return make_float2(lo, hi);
}

// ---------------- prep (stage 1 only): pack x as float4 (x,y,z,|p|^2) ------
__global__ __launch_bounds__(256) void prep_pts_kernel(const float* __restrict__ x, int b0)
{
    int t = blockIdx.x*256 + threadIdx.x;
    if (t >= NB*NN) return;
    size_t pt = (size_t)b0*NN + t;
    const float* src = x + pt*3;
    float px = src[0], py = src[1], pz = src[2];
    g_pts[pt] = make_float4(px, py, pz, px*px + py*py + pz*pz);
}

// ---------------- kNN v7: warp-per-query, enc-domain + redux inserts -------
// grid (NB, NN/8), 256 thr = 8 warps = 8 queries/block.
__global__ __launch_bounds__(256) void knn_kernel(int b0)
{
    __shared__ float4 pts[NN];
    int tid = threadIdx.x;
    int b = b0 + blockIdx.x;
    for (int j = tid; j < NN; j += 256)
        pts[j] = g_pts[(size_t)b*NN + j];
    __syncthreads();

    int w = tid >> 5, lane = tid & 31;
    int i = blockIdx.y*8 + w;
    float4 q = pts[i];
    float qx2 = 2.f*q.x, qy2 = 2.f*q.y, qz2 = 2.f*q.z, qw = q.w;

    unsigned be  = (lane < KNN) ? ENC_NEGINF : 0xFFFFFFFFu;
    int      bi  = 0;
    unsigned thr = ENC_NEGINF;

    for (int ch = 0; ch < NN/64; ch++){
        int j0 = ch*64 + lane;
        float4 p0 = pts[j0];
        float4 p1 = pts[j0 + 32];
        float t0 = fmaf(qz2, p0.z, -qw);
        t0 = fmaf(qy2, p0.y, t0);
        t0 = fmaf(qx2, p0.x, t0);
        unsigned e0 = fenc(t0 - p0.w);
        float t1 = fmaf(qz2, p1.z, -qw);
        t1 = fmaf(qy2, p1.y, t1);
        t1 = fmaf(qx2, p1.x, t1);
        unsigned e1 = fenc(t1 - p1.w);

        unsigned mask = __ballot_sync(FULLM, e0 > thr);
        while (mask){
            int src = __ffs(mask) - 1;
            mask &= mask - 1;
            unsigned e = __shfl_sync(FULLM, e0, src);
            if (e > thr){
                unsigned mv = __reduce_min_sync(FULLM, be);
                if (e > mv){
                    unsigned own = __ballot_sync(FULLM, be == mv);
                    int ml = __ffs(own) - 1;
                    if (lane == ml){ be = e; bi = j0 - lane + src; }
                }
                thr = mv;
            }
        }
        mask = __ballot_sync(FULLM, e1 > thr);
        while (mask){
            int src = __ffs(mask) - 1;
            mask &= mask - 1;
            unsigned e = __shfl_sync(FULLM, e1, src);
            if (e > thr){
                unsigned mv = __reduce_min_sync(FULLM, be);
                if (e > mv){
                    unsigned own = __ballot_sync(FULLM, be == mv);
                    int ml = __ffs(own) - 1;
                    if (lane == ml){ be = e; bi = j0 - lane + 32 + src; }
                }
                thr = mv;
            }
        }
    }
    if (lane < KNN)
        g_idx[((size_t)b*NN + i)*KNN + lane] = bi;
}

// ---------------- gemmYT v2: Y' = s*(x@Wlo^T), T' = s*(x@Wd^T)+b -----------
template<int C, int SEL>
__global__ __launch_bounds__(256) void gemmYT_kernel(
    const float* __restrict__ x, const float* __restrict__ W,
    const float* __restrict__ bng, const float* __restrict__ bnb,
    const float* __restrict__ bnm, const float* __restrict__ bnv, int b0)
{
    const float* __restrict__ xin = (SEL == 0) ? x : (SEL == 1) ? g_x1 : g_x2;

    __shared__ __align__(16) float Wlo[C*64];
    __shared__ __align__(16) float Wd [C*64];
    __shared__ __align__(16) float xS [32*C];

    int tid = threadIdx.x;
    size_t pt0 = (size_t)b0*NN + blockIdx.x*32;

    for (int t = tid; t < C*64; t += 256){
        int o = t & 63, c = t >> 6;
        float lo = W[(size_t)o*(2*C) + c];
        Wlo[c*64 + o] = lo;
        Wd [c*64 + o] = W[(size_t)o*(2*C) + C + c] - lo;
    }
    for (int t = tid; t < 32*C; t += 256){
        int p = t / C, c = t % C;
        xS[p*C + c] = xin[(pt0 + p)*C + c];
    }
    __syncthreads();

    int o0 = (tid & 15)*4;
    int p0 = (tid >> 4)*2, p1 = p0 + 1;

    float aY0[4]={0,0,0,0}, aT0[4]={0,0,0,0};
    float aY1[4]={0,0,0,0}, aT1[4]={0,0,0,0};

#pragma unroll 4
    for (int c = 0; c < C; c++){
        float4 wl = *(const float4*)&Wlo[c*64 + o0];
        float4 wd = *(const float4*)&Wd [c*64 + o0];
        float x0 = xS[p0*C + c];
        float x1 = xS[p1*C + c];
        aY0[0]=fmaf(x0,wl.x,aY0[0]); aY0[1]=fmaf(x0,wl.y,aY0[1]);
        aY0[2]=fmaf(x0,wl.z,aY0[2]); aY0[3]=fmaf(x0,wl.w,aY0[3]);
        aT0[0]=fmaf(x0,wd.x,aT0[0]); aT0[1]=fmaf(x0,wd.y,aT0[1]);
        aT0[2]=fmaf(x0,wd.z,aT0[2]); aT0[3]=fmaf(x0,wd.w,aT0[3]);
        aY1[0]=fmaf(x1,wl.x,aY1[0]); aY1[1]=fmaf(x1,wl.y,aY1[1]);
        aY1[2]=fmaf(x1,wl.z,aY1[2]); aY1[3]=fmaf(x1,wl.w,aY1[3]);
        aT1[0]=fmaf(x1,wd.x,aT1[0]); aT1[1]=fmaf(x1,wd.y,aT1[1]);
        aT1[2]=fmaf(x1,wd.z,aT1[2]); aT1[3]=fmaf(x1,wd.w,aT1[3]);
    }

    float4 gv = *(const float4*)&bng[o0];
    float4 bv = *(const float4*)&bnb[o0];
    float4 mv = *(const float4*)&bnm[o0];
    float4 vv = *(const float4*)&bnv[o0];
    float s[4], bo[4];
    s[0] = gv.x*rsqrtf(vv.x + EPSB); bo[0] = bv.x - mv.x*s[0];
    s[1] = gv.y*rsqrtf(vv.y + EPSB); bo[1] = bv.y - mv.y*s[1];
    s[2] = gv.z*rsqrtf(vv.z + EPSB); bo[2] = bv.z - mv.z*s[2];
    s[3] = gv.w*rsqrtf(vv.w + EPSB); bo[3] = bv.w - mv.w*s[3];

    float4 r;
    r = make_float4(s[0]*aY0[0], s[1]*aY0[1], s[2]*aY0[2], s[3]*aY0[3]);
    *(float4*)&g_Y[(pt0 + p0)*64 + o0] = r;
    r = make_float4(s[0]*aY1[0], s[1]*aY1[1], s[2]*aY1[2], s[3]*aY1[3]);
    *(float4*)&g_Y[(pt0 + p1)*64 + o0] = r;
    r = make_float4(fmaf(s[0],aT0[0],bo[0]), fmaf(s[1],aT0[1],bo[1]),
                    fmaf(s[2],aT0[2],bo[2]), fmaf(s[3],aT0[3],bo[3]));
    *(float4*)&g_T[(pt0 + p0)*64 + o0] = r;
    r = make_float4(fmaf(s[0],aT1[0],bo[0]), fmaf(s[1],aT1[1],bo[1]),
                    fmaf(s[2],aT1[2],bo[2]), fmaf(s[3],aT1[3],bo[3]));
    *(float4*)&g_T[(pt0 + p1)*64 + o0] = r;
}

// ---------------- edge_conv2 v2 (scalar 5x8): -> conv-b -> k-max -----------
template<int SEL_OUT>
__global__ __launch_bounds__(256) void edge_conv2_kernel(
    const float* __restrict__ Wb,
    const float* __restrict__ bng, const float* __restrict__ bnb,
    const float* __restrict__ bnm, const float* __restrict__ bnv, int b0)
{
    float* __restrict__ xout = (SEL_OUT == 1) ? g_x1 : g_x2;

    __shared__ __align__(16) float Ws[64*64];
    __shared__ __align__(16) float As[64*161];
    __shared__ __align__(16) float red[4*8*64];
    __shared__ int idxS[160];

    int tid = threadIdx.x;
    size_t pt0 = (size_t)b0*NN + blockIdx.x*8;

    for (int t = tid; t < 4096; t += 256){
        int o = t & 63, c = t >> 6;
        Ws[c*64 + o] = Wb[(size_t)o*64 + c];
    }
    if (tid < 160) idxS[tid] = g_idx[pt0*KNN + tid];
    __syncthreads();

    for (int e = tid; e < 160*64; e += 256){
        int r = e >> 6, c = e & 63;
        int p = r / KNN;
        size_t bb = (pt0 + p) >> 11;
        int j = idxS[r];
        float v = g_Y[(bb*NN + j)*64 + c] + g_T[(pt0 + p)*64 + c];
        As[c*161 + r] = lrelu(v);
    }

    int r5 = tid & 31;
    int og = (tid >> 5) * 8;

    float s2[8], b2[8];
#pragma unroll
    for (int q = 0; q < 8; q++){
        int o = og + q;
        float r = rsqrtf(bnv[o] + EPSB);
        s2[q] = bng[o]*r; b2[q] = bnb[o] - bnm[o]*s2[q];
    }
    __syncthreads();

    float acc[5][8];
#pragma unroll
    for (int i = 0; i < 5; i++)
#pragma unroll
        for (int q = 0; q < 8; q++) acc[i][q] = 0.f;

#pragma unroll 4
    for (int c = 0; c < 64; c++){
        float4 wA = *(const float4*)&Ws[c*64 + og];
        float4 wB = *(const float4*)&Ws[c*64 + og + 4];
        float a[5];
#pragma unroll
        for (int i = 0; i < 5; i++) a[i] = As[c*161 + r5*5 + i];
#pragma unroll
        for (int i = 0; i < 5; i++){
            acc[i][0]=fmaf(a[i],wA.x,acc[i][0]); acc[i][1]=fmaf(a[i],wA.y,acc[i][1]);
            acc[i][2]=fmaf(a[i],wA.z,acc[i][2]); acc[i][3]=fmaf(a[i],wA.w,acc[i][3]);
            acc[i][4]=fmaf(a[i],wB.x,acc[i][4]); acc[i][5]=fmaf(a[i],wB.y,acc[i][5]);
            acc[i][6]=fmaf(a[i],wB.z,acc[i][6]); acc[i][7]=fmaf(a[i],wB.w,acc[i][7]);
        }
    }

    int p    = r5 >> 2;
    int part = r5 & 3;
#pragma unroll
    for (int q = 0; q < 8; q++){
        float mx = -CUDART_INF_F;
#pragma unroll
        for (int i = 0; i < 5; i++)
            mx = fmaxf(mx, lrelu(fmaf(acc[i][q], s2[q], b2[q])));
        red[(part*8 + p)*64 + og + q] = mx;
    }
    __syncthreads();

    for (int t = tid; t < 512; t += 256){
        int pp = t >> 6, oo = t & 63;
        float m = red[(0*8 + pp)*64 + oo];
        m = fmaxf(m, red[(1*8 + pp)*64 + oo]);
        m = fmaxf(m, red[(2*8 + pp)*64 + oo]);
        m = fmaxf(m, red[(3*8 + pp)*64 + oo]);
        xout[(pt0 + pp)*64 + oo] = m;
    }

    // fused prep for the NEXT stage's kNN: pts = (c6,c7,c8,|p|^2)
    if (tid < 8){
        int pp = tid;
        float v[3];
#pragma unroll
        for (int c = 0; c < 3; c++){
            float m = red[(0*8 + pp)*64 + 6 + c];
            m = fmaxf(m, red[(1*8 + pp)*64 + 6 + c]);
            m = fmaxf(m, red[(2*8 + pp)*64 + 6 + c]);
            m = fmaxf(m, red[(3*8 + pp)*64 + 6 + c]);
            v[c] = m;
        }
        g_pts[pt0 + pp] = make_float4(v[0], v[1], v[2],
                                      v[0]*v[0] + v[1]*v[1] + v[2]*v[2]);
    }
}

// ---------------- edge_max (stage 3): x3 = max_k lrelu(Y'[j]+T'[i]) --------
__global__ __launch_bounds__(256) void edge_max_kernel(int b0)
{
    __shared__ int idxS[4*KNN];
    int tid = threadIdx.x;
    size_t pt0 = (size_t)b0*NN + blockIdx.x*4;
    if (tid < 4*KNN) idxS[tid] = g_idx[pt0*KNN + tid];
    __syncthreads();

    int p = tid >> 6, o = tid & 63;
    size_t pt = pt0 + p;
    size_t bb = pt >> 11;
    float tv = g_T[pt*64 + o];
    float m = -CUDART_INF_F;
#pragma unroll
    for (int k = 0; k < KNN; k++){
        int j = idxS[p*KNN + k];
        m = fmaxf(m, lrelu(g_Y[(bb*NN + j)*64 + o] + tv));
    }
    g_x3[pt*64 + o] = m;
}

// ---------------- init / final GEMM v3 (FFMA2) / outputs -------------------
__global__ void init_gmax_kernel(){
    int t = blockIdx.x*256 + threadIdx.x;
    if (t < BB*1024) g_gmax[t] = 0u;
}

__global__ __launch_bounds__(256) void final_kernel(
    const float* __restrict__ W6,
    const float* __restrict__ bn6g, const float* __restrict__ bn6b,
    const float* __restrict__ bn6m, const float* __restrict__ bn6v, int b0)
{
    extern __shared__ float dsm[];
    float* Bs = dsm;              // [192*68]
    float* As = dsm + 192*68;     // [192*68]
    __shared__ float ss6[64], sb6[64];
    __shared__ float red[64*16];

    int tid = threadIdx.x;
    int n0 = blockIdx.x*64;
    int bb = b0 + blockIdx.y;
    int mc = blockIdx.z;

    if (tid < 64){
        int o = n0 + tid;
        float r = rsqrtf(bn6v[o] + EPSB);
        ss6[tid] = bn6g[o]*r; sb6[tid] = bn6b[o] - bn6m[o]*ss6[tid];
    }

    for (int ch = 0; ch < 3; ch++)
        for (int t = tid; t < 4096; t += 256){
            int nn = t >> 6, c = t & 63;
            Bs[(ch*64 + c)*68 + nn] = W6[(size_t)(n0+nn)*192 + ch*64 + c];
        }
    __syncthreads();

    int tm = tid & 15, tn = tid >> 4;
    float s6[4], b6[4];
#pragma unroll
    for (int q = 0; q < 4; q++){ s6[q] = ss6[tn*4+q]; b6[q] = sb6[tn*4+q]; }

    float vmax[4] = {-CUDART_INF_F, -CUDART_INF_F, -CUDART_INF_F, -CUDART_INF_F};

    for (int mi = mc*8; mi < mc*8 + 8; mi++){
        size_t m1 = (size_t)bb*NN + mi*64;
        __syncthreads();
        {
            for (int t = tid; t < 4096; t += 256){
                int m = t >> 6, c = t & 63;
                As[(0*64 + c)*68 + m] = g_x1[(m1 + m)*64 + c];
            }
            for (int t = tid; t < 4096; t += 256){
                int m = t >> 6, c = t & 63;
                As[(1*64 + c)*68 + m] = g_x2[(m1 + m)*64 + c];
            }
            for (int t = tid; t < 4096; t += 256){
                int m = t >> 6, c = t & 63;
                As[(2*64 + c)*68 + m] = g_x3[(m1 + m)*64 + c];
            }
        }
        __syncthreads();

        unsigned long long acc2[4][2];
#pragma unroll
        for (int i = 0; i < 4; i++){ acc2[i][0] = 0ULL; acc2[i][1] = 0ULL; }

#pragma unroll 8
        for (int c = 0; c < 192; c++){
            float4 a = *(const float4*)&As[c*68 + tm*4];
            ulonglong2 bp = *(const ulonglong2*)&Bs[c*68 + tn*4];
            unsigned long long a0 = pack2(a.x), a1 = pack2(a.y),
                               a2 = pack2(a.z), a3 = pack2(a.w);
            fma2(acc2[0][0], a0, bp.x); fma2(acc2[0][1], a0, bp.y);
            fma2(acc2[1][0], a1, bp.x); fma2(acc2[1][1], a1, bp.y);
            fma2(acc2[2][0], a2, bp.x); fma2(acc2[2][1], a2, bp.y);
            fma2(acc2[3][0], a3, bp.x); fma2(acc2[3][1], a3, bp.y);
        }
#pragma unroll
        for (int mq = 0; mq < 4; mq++){
            float2 v0 = unpack2(acc2[mq][0]);
            float2 v1 = unpack2(acc2[mq][1]);
            vmax[0] = fmaxf(vmax[0], lrelu(fmaf(v0.x, s6[0], b6[0])));
            vmax[1] = fmaxf(vmax[1], lrelu(fmaf(v0.y, s6[1], b6[1])));
            vmax[2] = fmaxf(vmax[2], lrelu(fmaf(v1.x, s6[2], b6[2])));
            vmax[3] = fmaxf(vmax[3], lrelu(fmaf(v1.y, s6[3], b6[3])));
        }
    }

    __syncthreads();
#pragma unroll
    for (int nq = 0; nq < 4; nq++) red[(tn*4+nq)*16 + tm] = vmax[nq];
    __syncthreads();
    if (tid < 64){
        float mx = -CUDART_INF_F;
#pragma unroll
        for (int t = 0; t < 16; t++) mx = fmaxf(mx, red[tid*16 + t]);
        atomicMax(&g_gmax[bb*1024 + n0 + tid], fencs(mx));
    }
}

__global__ void feat_kernel(float* __restrict__ out, int b0){
    int t = b0*1024 + blockIdx.x*256 + threadIdx.x;
    out[t] = fdec(g_gmax[t]);
}

// ---------------- x4^T via smem transpose ----------------------------------
__global__ __launch_bounds__(256) void x4t_kernel(float* __restrict__ out, int b0)
{
    __shared__ float T[64*65];
    int tid = threadIdx.x;
    int n0 = blockIdx.x*64;
    int bb = b0 + blockIdx.y;
    int ch = blockIdx.z;
    const float* src = (ch == 0) ? g_x1 : (ch == 1) ? g_x2 : g_x3;

    for (int t = tid; t < 4096; t += 256){
        int c = t & 63, n = t >> 6;
        T[c*65 + n] = src[((size_t)bb*NN + n0 + n)*64 + c];
    }
    __syncthreads();
    size_t base = (size_t)BB*1024 + (size_t)bb*192*NN + (size_t)ch*64*NN;
    for (int t = tid; t < 4096; t += 256){
        int n = t & 63, c = t >> 6;
        out[base + (size_t)c*NN + n0 + n] = T[c*65 + n];
    }
}

// ---------------- launch: two independent 4-batch pipelines ----------------
extern "C" void kernel_launch(void* const* d_in, const int* in_sizes, int n_in,
                              void* d_out, int out_size)
{
    const float* x    = (const float*)d_in[0];
    const float* W1   = (const float*)d_in[1];
    const float* W2   = (const float*)d_in[2];
    const float* W3   = (const float*)d_in[3];
    const float* W4   = (const float*)d_in[4];
    const float* W5   = (const float*)d_in[5];
    const float* W6   = (const float*)d_in[6];
    const float* bng  = (const float*)d_in[7];
    const float* bnb  = (const float*)d_in[8];
    const float* bnm  = (const float*)d_in[9];
    const float* bnv  = (const float*)d_in[10];
    const float* bn6g = (const float*)d_in[11];
    const float* bn6b = (const float*)d_in[12];
    const float* bn6m = (const float*)d_in[13];
    const float* bn6v = (const float*)d_in[14];
    float* out = (float*)d_out;

    static cudaStream_t s1 = nullptr;
    static cudaEvent_t evRoot, evEnd;
    if (!s1){
        cudaStreamCreateWithFlags(&s1, cudaStreamNonBlocking);
        cudaEventCreateWithFlags(&evRoot, cudaEventDisableTiming);
        cudaEventCreateWithFlags(&evEnd,  cudaEventDisableTiming);
        cudaFuncSetAttribute(final_kernel,
            cudaFuncAttributeMaxDynamicSharedMemorySize, 2*192*68*4);
    }
    const int FSMEM = 2*192*68*4;

    init_gmax_kernel<<<32, 256>>>();                                   // idx 0
    cudaEventRecord(evRoot, 0);
    cudaStreamWaitEvent(s1, evRoot, 0);

    // Pipeline A: batches 0-3 on stream 0; Pipeline B: batches 4-7 on s1.
    // Launch calls interleaved; in-stream order carries all dependencies.

    // Stage 1
    prep_pts_kernel<<<NB*NN/256, 256, 0, 0 >>>(x, 0);                  // idx 1
    prep_pts_kernel<<<NB*NN/256, 256, 0, s1>>>(x, NB);                 // idx 2
    knn_kernel<<<dim3(NB, NN/8), 256, 0, 0 >>>(0);                     // idx 3 <- ncu
    knn_kernel<<<dim3(NB, NN/8), 256, 0, s1>>>(NB);
    gemmYT_kernel<3,0><<<NB*NN/32, 256, 0, 0 >>>(x, W1, bng, bnb, bnm, bnv, 0);
    gemmYT_kernel<3,0><<<NB*NN/32, 256, 0, s1>>>(x, W1, bng, bnb, bnm, bnv, NB);
    edge_conv2_kernel<1><<<NB*NN/8, 256, 0, 0 >>>(W2, bng+64, bnb+64, bnm+64, bnv+64, 0);
    edge_conv2_kernel<1><<<NB*NN/8, 256, 0, s1>>>(W2, bng+64, bnb+64, bnm+64, bnv+64, NB);

    // Stage 2
    knn_kernel<<<dim3(NB, NN/8), 256, 0, 0 >>>(0);
    knn_kernel<<<dim3(NB, NN/8), 256, 0, s1>>>(NB);
    gemmYT_kernel<64,1><<<NB*NN/32, 256, 0, 0 >>>(x, W3, bng+2*64, bnb+2*64, bnm+2*64, bnv+2*64, 0);
    gemmYT_kernel<64,1><<<NB*NN/32, 256, 0, s1>>>(x, W3, bng+2*64, bnb+2*64, bnm+2*64, bnv+2*64, NB);
    edge_conv2_kernel<2><<<NB*NN/8, 256, 0, 0 >>>(W4, bng+3*64, bnb+3*64, bnm+3*64, bnv+3*64, 0);
    edge_conv2_kernel<2><<<NB*NN/8, 256, 0, s1>>>(W4, bng+3*64, bnb+3*64, bnm+3*64, bnv+3*64, NB);

    // Stage 3
    knn_kernel<<<dim3(NB, NN/8), 256, 0, 0 >>>(0);
    knn_kernel<<<dim3(NB, NN/8), 256, 0, s1>>>(NB);
    gemmYT_kernel<64,2><<<NB*NN/32, 256, 0, 0 >>>(x, W5, bng+4*64, bnb+4*64, bnm+4*64, bnv+4*64, 0);
    gemmYT_kernel<64,2><<<NB*NN/32, 256, 0, s1>>>(x, W5, bng+4*64, bnb+4*64, bnm+4*64, bnv+4*64, NB);
    edge_max_kernel<<<NB*NN/4, 256, 0, 0 >>>(0);
    edge_max_kernel<<<NB*NN/4, 256, 0, s1>>>(NB);

    // Final + outputs
    final_kernel<<<dim3(1024/64, NB, 4), 256, FSMEM, 0 >>>(W6, bn6g, bn6b, bn6m, bn6v, 0);
    final_kernel<<<dim3(1024/64, NB, 4), 256, FSMEM, s1>>>(W6, bn6g, bn6b, bn6m, bn6v, NB);
    x4t_kernel<<<dim3(NN/64, NB, 3), 256, 0, 0 >>>(out, 0);
    x4t_kernel<<<dim3(NN/64, NB, 3), 256, 0, s1>>>(out, NB);
    feat_kernel<<<NB*1024/256, 256, 0, 0 >>>(out, 0);
    feat_kernel<<<NB*1024/256, 256, 0, s1>>>(out, NB);

    cudaEventRecord(evEnd, s1);
    cudaStreamWaitEvent(0, evEnd, 0);   // join pipeline B into capture stream
}

// round 16
// speedup vs baseline: 1.0879x; 1.0125x over previous
#include <cuda_runtime.h>
#include <math_constants.h>

#define BB 8
#define NB 2              // batches per pipeline (4 pipelines)
#define NN 2048
#define KNN 20
#define NTOT (BB*NN)
#define EPSB 1e-5f
#define FULLM 0xFFFFFFFFu
#define ENC_NEGINF 0x007FFFFFu   // fenc(-INF)

// ---------------- scratch (device globals; no allocation allowed) ----------
__device__ int      g_idx[NTOT*KNN];
__device__ float    g_x1[NTOT*64];
__device__ float    g_x2[NTOT*64];
__device__ float    g_x3[NTOT*64];
__device__ float    g_Y[NTOT*64];
__device__ float    g_T[NTOT*64];
__device__ float4   g_pts[NTOT];
__device__ unsigned g_gmax[BB*1024];

__device__ __forceinline__ float lrelu(float z){ return z >= 0.f ? z : 0.2f*z; }
__device__ __forceinline__ unsigned fenc(float f){
    unsigned u = __float_as_uint(f);
    return u ^ ((unsigned)((int)u >> 31) | 0x80000000u);
}
__device__ __forceinline__ unsigned fencs(float f){
    unsigned u = __float_as_uint(f);
    return (u & 0x80000000u) ? ~u : (u | 0x80000000u);
}
__device__ __forceinline__ float fdec(unsigned e){
    return (e & 0x80000000u) ? __uint_as_float(e ^ 0x80000000u) : __uint_as_float(~e);
}

// ---------------- packed f32x2 helpers (FFMA2 — used in final only) --------
__device__ __forceinline__ unsigned long long pack2(float v){
    unsigned long long r;
    asm("mov.b64 %0, {%1, %1};" : "=l"(r) : "f"(v));
    return r;
}
__device__ __forceinline__ void fma2(unsigned long long& d,
                                     unsigned long long a, unsigned long long b){
    asm("fma.rn.f32x2 %0, %1, %2, %0;" : "+l"(d) : "l"(a), "l"(b));
}
__device__ __forceinline__ float2 unpack2(unsigned long long v){
    float lo, hi;
    asm("mov.b64 {%0, %1}, %2;" : "=f"(lo), "=f"(hi) : "l"(v));
    return make_float2(lo, hi);
}

// ---------------- prep (stage 1 only): pack x as float4 (x,y,z,|p|^2) ------
__global__ __launch_bounds__(256) void prep_pts_kernel(const float* __restrict__ x, int b0)
{
    int t = blockIdx.x*256 + threadIdx.x;
    if (t >= NB*NN) return;
    size_t pt = (size_t)b0*NN + t;
    const float* src = x + pt*3;
    float px = src[0], py = src[1], pz = src[2];
    g_pts[pt] = make_float4(px, py, pz, px*px + py*py + pz*pz);
}

// ---------------- kNN v7: warp-per-query, enc-domain + redux inserts -------
__global__ __launch_bounds__(256) void knn_kernel(int b0)
{
    __shared__ float4 pts[NN];
    int tid = threadIdx.x;
    int b = b0 + blockIdx.x;
    for (int j = tid; j < NN; j += 256)
        pts[j] = g_pts[(size_t)b*NN + j];
    __syncthreads();

    int w = tid >> 5, lane = tid & 31;
    int i = blockIdx.y*8 + w;
    float4 q = pts[i];
    float qx2 = 2.f*q.x, qy2 = 2.f*q.y, qz2 = 2.f*q.z, qw = q.w;

    unsigned be  = (lane < KNN) ? ENC_NEGINF : 0xFFFFFFFFu;
    int      bi  = 0;
    unsigned thr = ENC_NEGINF;

    for (int ch = 0; ch < NN/64; ch++){
        int j0 = ch*64 + lane;
        float4 p0 = pts[j0];
        float4 p1 = pts[j0 + 32];
        float t0 = fmaf(qz2, p0.z, -qw);
        t0 = fmaf(qy2, p0.y, t0);
        t0 = fmaf(qx2, p0.x, t0);
        unsigned e0 = fenc(t0 - p0.w);
        float t1 = fmaf(qz2, p1.z, -qw);
        t1 = fmaf(qy2, p1.y, t1);
        t1 = fmaf(qx2, p1.x, t1);
        unsigned e1 = fenc(t1 - p1.w);

        unsigned mask = __ballot_sync(FULLM, e0 > thr);
        while (mask){
            int src = __ffs(mask) - 1;
            mask &= mask - 1;
            unsigned e = __shfl_sync(FULLM, e0, src);
            if (e > thr){
                unsigned mv = __reduce_min_sync(FULLM, be);
                if (e > mv){
                    unsigned own = __ballot_sync(FULLM, be == mv);
                    int ml = __ffs(own) - 1;
                    if (lane == ml){ be = e; bi = j0 - lane + src; }
                }
                thr = mv;
            }
        }
        mask = __ballot_sync(FULLM, e1 > thr);
        while (mask){
            int src = __ffs(mask) - 1;
            mask &= mask - 1;
            unsigned e = __shfl_sync(FULLM, e1, src);
            if (e > thr){
                unsigned mv = __reduce_min_sync(FULLM, be);
                if (e > mv){
                    unsigned own = __ballot_sync(FULLM, be == mv);
                    int ml = __ffs(own) - 1;
                    if (lane == ml){ be = e; bi = j0 - lane + 32 + src; }
                }
                thr = mv;
            }
        }
    }
    if (lane < KNN)
        g_idx[((size_t)b*NN + i)*KNN + lane] = bi;
}

// ---------------- gemmYT v2: Y' = s*(x@Wlo^T), T' = s*(x@Wd^T)+b -----------
template<int C, int SEL>
__global__ __launch_bounds__(256) void gemmYT_kernel(
    const float* __restrict__ x, const float* __restrict__ W,
    const float* __restrict__ bng, const float* __restrict__ bnb,
    const float* __restrict__ bnm, const float* __restrict__ bnv, int b0)
{
    const float* __restrict__ xin = (SEL == 0) ? x : (SEL == 1) ? g_x1 : g_x2;

    __shared__ __align__(16) float Wlo[C*64];
    __shared__ __align__(16) float Wd [C*64];
    __shared__ __align__(16) float xS [32*C];

    int tid = threadIdx.x;
    size_t pt0 = (size_t)b0*NN + blockIdx.x*32;

    for (int t = tid; t < C*64; t += 256){
        int o = t & 63, c = t >> 6;
        float lo = W[(size_t)o*(2*C) + c];
        Wlo[c*64 + o] = lo;
        Wd [c*64 + o] = W[(size_t)o*(2*C) + C + c] - lo;
    }
    for (int t = tid; t < 32*C; t += 256){
        int p = t / C, c = t % C;
        xS[p*C + c] = xin[(pt0 + p)*C + c];
    }
    __syncthreads();

    int o0 = (tid & 15)*4;
    int p0 = (tid >> 4)*2, p1 = p0 + 1;

    float aY0[4]={0,0,0,0}, aT0[4]={0,0,0,0};
    float aY1[4]={0,0,0,0}, aT1[4]={0,0,0,0};

#pragma unroll 4
    for (int c = 0; c < C; c++){
        float4 wl = *(const float4*)&Wlo[c*64 + o0];
        float4 wd = *(const float4*)&Wd [c*64 + o0];
        float x0 = xS[p0*C + c];
        float x1 = xS[p1*C + c];
        aY0[0]=fmaf(x0,wl.x,aY0[0]); aY0[1]=fmaf(x0,wl.y,aY0[1]);
        aY0[2]=fmaf(x0,wl.z,aY0[2]); aY0[3]=fmaf(x0,wl.w,aY0[3]);
        aT0[0]=fmaf(x0,wd.x,aT0[0]); aT0[1]=fmaf(x0,wd.y,aT0[1]);
        aT0[2]=fmaf(x0,wd.z,aT0[2]); aT0[3]=fmaf(x0,wd.w,aT0[3]);
        aY1[0]=fmaf(x1,wl.x,aY1[0]); aY1[1]=fmaf(x1,wl.y,aY1[1]);
        aY1[2]=fmaf(x1,wl.z,aY1[2]); aY1[3]=fmaf(x1,wl.w,aY1[3]);
        aT1[0]=fmaf(x1,wd.x,aT1[0]); aT1[1]=fmaf(x1,wd.y,aT1[1]);
        aT1[2]=fmaf(x1,wd.z,aT1[2]); aT1[3]=fmaf(x1,wd.w,aT1[3]);
    }

    float4 gv = *(const float4*)&bng[o0];
    float4 bv = *(const float4*)&bnb[o0];
    float4 mv = *(const float4*)&bnm[o0];
    float4 vv = *(const float4*)&bnv[o0];
    float s[4], bo[4];
    s[0] = gv.x*rsqrtf(vv.x + EPSB); bo[0] = bv.x - mv.x*s[0];
    s[1] = gv.y*rsqrtf(vv.y + EPSB); bo[1] = bv.y - mv.y*s[1];
    s[2] = gv.z*rsqrtf(vv.z + EPSB); bo[2] = bv.z - mv.z*s[2];
    s[3] = gv.w*rsqrtf(vv.w + EPSB); bo[3] = bv.w - mv.w*s[3];

    float4 r;
    r = make_float4(s[0]*aY0[0], s[1]*aY0[1], s[2]*aY0[2], s[3]*aY0[3]);
    *(float4*)&g_Y[(pt0 + p0)*64 + o0] = r;
    r = make_float4(s[0]*aY1[0], s[1]*aY1[1], s[2]*aY1[2], s[3]*aY1[3]);
    *(float4*)&g_Y[(pt0 + p1)*64 + o0] = r;
    r = make_float4(fmaf(s[0],aT0[0],bo[0]), fmaf(s[1],aT0[1],bo[1]),
                    fmaf(s[2],aT0[2],bo[2]), fmaf(s[3],aT0[3],bo[3]));
    *(float4*)&g_T[(pt0 + p0)*64 + o0] = r;
    r = make_float4(fmaf(s[0],aT1[0],bo[0]), fmaf(s[1],aT1[1],bo[1]),
                    fmaf(s[2],aT1[2],bo[2]), fmaf(s[3],aT1[3],bo[3]));
    *(float4*)&g_T[(pt0 + p1)*64 + o0] = r;
}

// ---------------- edge_conv2 v2 (scalar 5x8): -> conv-b -> k-max -----------
template<int SEL_OUT>
__global__ __launch_bounds__(256) void edge_conv2_kernel(
    const float* __restrict__ Wb,
    const float* __restrict__ bng, const float* __restrict__ bnb,
    const float* __restrict__ bnm, const float* __restrict__ bnv, int b0)
{
    float* __restrict__ xout = (SEL_OUT == 1) ? g_x1 : g_x2;

    __shared__ __align__(16) float Ws[64*64];
    __shared__ __align__(16) float As[64*161];
    __shared__ __align__(16) float red[4*8*64];
    __shared__ int idxS[160];

    int tid = threadIdx.x;
    size_t pt0 = (size_t)b0*NN + blockIdx.x*8;

    for (int t = tid; t < 4096; t += 256){
        int o = t & 63, c = t >> 6;
        Ws[c*64 + o] = Wb[(size_t)o*64 + c];
    }
    if (tid < 160) idxS[tid] = g_idx[pt0*KNN + tid];
    __syncthreads();

    for (int e = tid; e < 160*64; e += 256){
        int r = e >> 6, c = e & 63;
        int p = r / KNN;
        size_t bb = (pt0 + p) >> 11;
        int j = idxS[r];
        float v = g_Y[(bb*NN + j)*64 + c] + g_T[(pt0 + p)*64 + c];
        As[c*161 + r] = lrelu(v);
    }

    int r5 = tid & 31;
    int og = (tid >> 5) * 8;

    float s2[8], b2[8];
#pragma unroll
    for (int q = 0; q < 8; q++){
        int o = og + q;
        float r = rsqrtf(bnv[o] + EPSB);
        s2[q] = bng[o]*r; b2[q] = bnb[o] - bnm[o]*s2[q];
    }
    __syncthreads();

    float acc[5][8];
#pragma unroll
    for (int i = 0; i < 5; i++)
#pragma unroll
        for (int q = 0; q < 8; q++) acc[i][q] = 0.f;

#pragma unroll 4
    for (int c = 0; c < 64; c++){
        float4 wA = *(const float4*)&Ws[c*64 + og];
        float4 wB = *(const float4*)&Ws[c*64 + og + 4];
        float a[5];
#pragma unroll
        for (int i = 0; i < 5; i++) a[i] = As[c*161 + r5*5 + i];
#pragma unroll
        for (int i = 0; i < 5; i++){
            acc[i][0]=fmaf(a[i],wA.x,acc[i][0]); acc[i][1]=fmaf(a[i],wA.y,acc[i][1]);
            acc[i][2]=fmaf(a[i],wA.z,acc[i][2]); acc[i][3]=fmaf(a[i],wA.w,acc[i][3]);
            acc[i][4]=fmaf(a[i],wB.x,acc[i][4]); acc[i][5]=fmaf(a[i],wB.y,acc[i][5]);
            acc[i][6]=fmaf(a[i],wB.z,acc[i][6]); acc[i][7]=fmaf(a[i],wB.w,acc[i][7]);
        }
    }

    int p    = r5 >> 2;
    int part = r5 & 3;
#pragma unroll
    for (int q = 0; q < 8; q++){
        float mx = -CUDART_INF_F;
#pragma unroll
        for (int i = 0; i < 5; i++)
            mx = fmaxf(mx, lrelu(fmaf(acc[i][q], s2[q], b2[q])));
        red[(part*8 + p)*64 + og + q] = mx;
    }
    __syncthreads();

    for (int t = tid; t < 512; t += 256){
        int pp = t >> 6, oo = t & 63;
        float m = red[(0*8 + pp)*64 + oo];
        m = fmaxf(m, red[(1*8 + pp)*64 + oo]);
        m = fmaxf(m, red[(2*8 + pp)*64 + oo]);
        m = fmaxf(m, red[(3*8 + pp)*64 + oo]);
        xout[(pt0 + pp)*64 + oo] = m;
    }

    // fused prep for the NEXT stage's kNN: pts = (c6,c7,c8,|p|^2)
    if (tid < 8){
        int pp = tid;
        float v[3];
#pragma unroll
        for (int c = 0; c < 3; c++){
            float m = red[(0*8 + pp)*64 + 6 + c];
            m = fmaxf(m, red[(1*8 + pp)*64 + 6 + c]);
            m = fmaxf(m, red[(2*8 + pp)*64 + 6 + c]);
            m = fmaxf(m, red[(3*8 + pp)*64 + 6 + c]);
            v[c] = m;
        }
        g_pts[pt0 + pp] = make_float4(v[0], v[1], v[2],
                                      v[0]*v[0] + v[1]*v[1] + v[2]*v[2]);
    }
}

// ---------------- edge_max (stage 3): x3 = max_k lrelu(Y'[j]+T'[i]) --------
__global__ __launch_bounds__(256) void edge_max_kernel(int b0)
{
    __shared__ int idxS[4*KNN];
    int tid = threadIdx.x;
    size_t pt0 = (size_t)b0*NN + blockIdx.x*4;
    if (tid < 4*KNN) idxS[tid] = g_idx[pt0*KNN + tid];
    __syncthreads();

    int p = tid >> 6, o = tid & 63;
    size_t pt = pt0 + p;
    size_t bb = pt >> 11;
    float tv = g_T[pt*64 + o];
    float m = -CUDART_INF_F;
#pragma unroll
    for (int k = 0; k < KNN; k++){
        int j = idxS[p*KNN + k];
        m = fmaxf(m, lrelu(g_Y[(bb*NN + j)*64 + o] + tv));
    }
    g_x3[pt*64 + o] = m;
}

// ---------------- init / final GEMM v3 (FFMA2) / outputs -------------------
__global__ void init_gmax_kernel(){
    int t = blockIdx.x*256 + threadIdx.x;
    if (t < BB*1024) g_gmax[t] = 0u;
}

__global__ __launch_bounds__(256) void final_kernel(
    const float* __restrict__ W6,
    const float* __restrict__ bn6g, const float* __restrict__ bn6b,
    const float* __restrict__ bn6m, const float* __restrict__ bn6v, int b0)
{
    extern __shared__ float dsm[];
    float* Bs = dsm;              // [192*68]
    float* As = dsm + 192*68;     // [192*68]
    __shared__ float ss6[64], sb6[64];
    __shared__ float red[64*16];

    int tid = threadIdx.x;
    int n0 = blockIdx.x*64;
    int bb = b0 + blockIdx.y;
    int mc = blockIdx.z;

    if (tid < 64){
        int o = n0 + tid;
        float r = rsqrtf(bn6v[o] + EPSB);
        ss6[tid] = bn6g[o]*r; sb6[tid] = bn6b[o] - bn6m[o]*ss6[tid];
    }

    for (int ch = 0; ch < 3; ch++)
        for (int t = tid; t < 4096; t += 256){
            int nn = t >> 6, c = t & 63;
            Bs[(ch*64 + c)*68 + nn] = W6[(size_t)(n0+nn)*192 + ch*64 + c];
        }
    __syncthreads();

    int tm = tid & 15, tn = tid >> 4;
    float s6[4], b6[4];
#pragma unroll
    for (int q = 0; q < 4; q++){ s6[q] = ss6[tn*4+q]; b6[q] = sb6[tn*4+q]; }

    float vmax[4] = {-CUDART_INF_F, -CUDART_INF_F, -CUDART_INF_F, -CUDART_INF_F};

    for (int mi = mc*8; mi < mc*8 + 8; mi++){
        size_t m1 = (size_t)bb*NN + mi*64;
        __syncthreads();
        {
            for (int t = tid; t < 4096; t += 256){
                int m = t >> 6, c = t & 63;
                As[(0*64 + c)*68 + m] = g_x1[(m1 + m)*64 + c];
            }
            for (int t = tid; t < 4096; t += 256){
                int m = t >> 6, c = t & 63;
                As[(1*64 + c)*68 + m] = g_x2[(m1 + m)*64 + c];
            }
            for (int t = tid; t < 4096; t += 256){
                int m = t >> 6, c = t & 63;
                As[(2*64 + c)*68 + m] = g_x3[(m1 + m)*64 + c];
            }
        }
        __syncthreads();

        unsigned long long acc2[4][2];
#pragma unroll
        for (int i = 0; i < 4; i++){ acc2[i][0] = 0ULL; acc2[i][1] = 0ULL; }

#pragma unroll 8
        for (int c = 0; c < 192; c++){
            float4 a = *(const float4*)&As[c*68 + tm*4];
            ulonglong2 bp = *(const ulonglong2*)&Bs[c*68 + tn*4];
            unsigned long long a0 = pack2(a.x), a1 = pack2(a.y),
                               a2 = pack2(a.z), a3 = pack2(a.w);
            fma2(acc2[0][0], a0, bp.x); fma2(acc2[0][1], a0, bp.y);
            fma2(acc2[1][0], a1, bp.x); fma2(acc2[1][1], a1, bp.y);
            fma2(acc2[2][0], a2, bp.x); fma2(acc2[2][1], a2, bp.y);
            fma2(acc2[3][0], a3, bp.x); fma2(acc2[3][1], a3, bp.y);
        }
#pragma unroll
        for (int mq = 0; mq < 4; mq++){
            float2 v0 = unpack2(acc2[mq][0]);
            float2 v1 = unpack2(acc2[mq][1]);
            vmax[0] = fmaxf(vmax[0], lrelu(fmaf(v0.x, s6[0], b6[0])));
            vmax[1] = fmaxf(vmax[1], lrelu(fmaf(v0.y, s6[1], b6[1])));
            vmax[2] = fmaxf(vmax[2], lrelu(fmaf(v1.x, s6[2], b6[2])));
            vmax[3] = fmaxf(vmax[3], lrelu(fmaf(v1.y, s6[3], b6[3])));
        }
    }

    __syncthreads();
#pragma unroll
    for (int nq = 0; nq < 4; nq++) red[(tn*4+nq)*16 + tm] = vmax[nq];
    __syncthreads();
    if (tid < 64){
        float mx = -CUDART_INF_F;
#pragma unroll
        for (int t = 0; t < 16; t++) mx = fmaxf(mx, red[tid*16 + t]);
        atomicMax(&g_gmax[bb*1024 + n0 + tid], fencs(mx));
    }
}

__global__ void feat_kernel(float* __restrict__ out, int b0){
    int t = b0*1024 + blockIdx.x*256 + threadIdx.x;
    out[t] = fdec(g_gmax[t]);
}

// ---------------- x4^T via smem transpose ----------------------------------
__global__ __launch_bounds__(256) void x4t_kernel(float* __restrict__ out, int b0)
{
    __shared__ float T[64*65];
    int tid = threadIdx.x;
    int n0 = blockIdx.x*64;
    int bb = b0 + blockIdx.y;
    int ch = blockIdx.z;
    const float* src = (ch == 0) ? g_x1 : (ch == 1) ? g_x2 : g_x3;

    for (int t = tid; t < 4096; t += 256){
        int c = t & 63, n = t >> 6;
        T[c*65 + n] = src[((size_t)bb*NN + n0 + n)*64 + c];
    }
    __syncthreads();
    size_t base = (size_t)BB*1024 + (size_t)bb*192*NN + (size_t)ch*64*NN;
    for (int t = tid; t < 4096; t += 256){
        int n = t & 63, c = t >> 6;
        out[base + (size_t)c*NN + n0 + n] = T[c*65 + n];
    }
}

// ---------------- launch: four independent 2-batch pipelines ---------------
extern "C" void kernel_launch(void* const* d_in, const int* in_sizes, int n_in,
                              void* d_out, int out_size)
{
    const float* x    = (const float*)d_in[0];
    const float* W1   = (const float*)d_in[1];
    const float* W2   = (const float*)d_in[2];
    const float* W3   = (const float*)d_in[3];
    const float* W4   = (const float*)d_in[4];
    const float* W5   = (const float*)d_in[5];
    const float* W6   = (const float*)d_in[6];
    const float* bng  = (const float*)d_in[7];
    const float* bnb  = (const float*)d_in[8];
    const float* bnm  = (const float*)d_in[9];
    const float* bnv  = (const float*)d_in[10];
    const float* bn6g = (const float*)d_in[11];
    const float* bn6b = (const float*)d_in[12];
    const float* bn6m = (const float*)d_in[13];
    const float* bn6v = (const float*)d_in[14];
    float* out = (float*)d_out;

    static cudaStream_t sx[3] = {nullptr, nullptr, nullptr};
    static cudaEvent_t evRoot, evEnd[3];
    if (!sx[0]){
        for (int i = 0; i < 3; i++){
            cudaStreamCreateWithFlags(&sx[i], cudaStreamNonBlocking);
            cudaEventCreateWithFlags(&evEnd[i], cudaEventDisableTiming);
        }
        cudaEventCreateWithFlags(&evRoot, cudaEventDisableTiming);
        cudaFuncSetAttribute(final_kernel,
            cudaFuncAttributeMaxDynamicSharedMemorySize, 2*192*68*4);
    }
    const int FSMEM = 2*192*68*4;
    cudaStream_t st[4] = {(cudaStream_t)0, sx[0], sx[1], sx[2]};

    init_gmax_kernel<<<32, 256>>>();
    cudaEventRecord(evRoot, 0);
    for (int i = 1; i < 4; i++) cudaStreamWaitEvent(st[i], evRoot, 0);

    // 4 pipelines, batches [2i, 2i+2). In-stream order carries dependencies.
    for (int i = 0; i < 4; i++)
        prep_pts_kernel<<<NB*NN/256, 256, 0, st[i]>>>(x, NB*i);
    for (int i = 0; i < 4; i++)
        knn_kernel<<<dim3(NB, NN/8), 256, 0, st[i]>>>(NB*i);
    for (int i = 0; i < 4; i++)
        gemmYT_kernel<3,0><<<NB*NN/32, 256, 0, st[i]>>>(x, W1, bng, bnb, bnm, bnv, NB*i);
    for (int i = 0; i < 4; i++)
        edge_conv2_kernel<1><<<NB*NN/8, 256, 0, st[i]>>>(W2, bng+64, bnb+64, bnm+64, bnv+64, NB*i);

    for (int i = 0; i < 4; i++)
        knn_kernel<<<dim3(NB, NN/8), 256, 0, st[i]>>>(NB*i);
    for (int i = 0; i < 4; i++)
        gemmYT_kernel<64,1><<<NB*NN/32, 256, 0, st[i]>>>(x, W3, bng+2*64, bnb+2*64, bnm+2*64, bnv+2*64, NB*i);
    for (int i = 0; i < 4; i++)
        edge_conv2_kernel<2><<<NB*NN/8, 256, 0, st[i]>>>(W4, bng+3*64, bnb+3*64, bnm+3*64, bnv+3*64, NB*i);

    for (int i = 0; i < 4; i++)
        knn_kernel<<<dim3(NB, NN/8), 256, 0, st[i]>>>(NB*i);
    for (int i = 0; i < 4; i++)
        gemmYT_kernel<64,2><<<NB*NN/32, 256, 0, st[i]>>>(x, W5, bng+4*64, bnb+4*64, bnm+4*64, bnv+4*64, NB*i);
    for (int i = 0; i < 4; i++)
        edge_max_kernel<<<NB*NN/4, 256, 0, st[i]>>>(NB*i);

    for (int i = 0; i < 4; i++)
        final_kernel<<<dim3(1024/64, NB, 4), 256, FSMEM, st[i]>>>(W6, bn6g, bn6b, bn6m, bn6v, NB*i);
    for (int i = 0; i < 4; i++)
        x4t_kernel<<<dim3(NN/64, NB, 3), 256, 0, st[i]>>>(out, NB*i);
    for (int i = 0; i < 4; i++)
        feat_kernel<<<NB*1024/256, 256, 0, st[i]>>>(out, NB*i);

    for (int i = 1; i < 4; i++){
        cudaEventRecord(evEnd[i-1], st[i]);
        cudaStreamWaitEvent(0, evEnd[i-1], 0);
    }
}

// round 17
// speedup vs baseline: 1.0890x; 1.0010x over previous
#include <cuda_runtime.h>
#include <math_constants.h>

#define BB 8
#define NB 2              // batches per pipeline (4 pipelines)
#define NN 2048
#define KNN 20
#define NTOT (BB*NN)
#define EPSB 1e-5f
#define FULLM 0xFFFFFFFFu
#define ENC_NEGINF 0x007FFFFFu   // fenc(-INF)

// ---------------- scratch (device globals; no allocation allowed) ----------
__device__ int      g_idx[NTOT*KNN];
__device__ float    g_x1[NTOT*64];
__device__ float    g_x2[NTOT*64];
__device__ float    g_x3[NTOT*64];
__device__ float    g_Y[NTOT*64];
__device__ float    g_T[NTOT*64];
__device__ float4   g_pts[NTOT];
__device__ unsigned g_gmax[BB*1024];

__device__ __forceinline__ float lrelu(float z){ return z >= 0.f ? z : 0.2f*z; }
__device__ __forceinline__ unsigned fenc(float f){
    unsigned u = __float_as_uint(f);
    return u ^ ((unsigned)((int)u >> 31) | 0x80000000u);
}
__device__ __forceinline__ unsigned fencs(float f){
    unsigned u = __float_as_uint(f);
    return (u & 0x80000000u) ? ~u : (u | 0x80000000u);
}
__device__ __forceinline__ float fdec(unsigned e){
    return (e & 0x80000000u) ? __uint_as_float(e ^ 0x80000000u) : __uint_as_float(~e);
}

// ---------------- packed f32x2 helpers (FFMA2 — used in final only) --------
__device__ __forceinline__ unsigned long long pack2(float v){
    unsigned long long r;
    asm("mov.b64 %0, {%1, %1};" : "=l"(r) : "f"(v));
    return r;
}
__device__ __forceinline__ void fma2(unsigned long long& d,
                                     unsigned long long a, unsigned long long b){
    asm("fma.rn.f32x2 %0, %1, %2, %0;" : "+l"(d) : "l"(a), "l"(b));
}
__device__ __forceinline__ float2 unpack2(unsigned long long v){
    float lo, hi;
    asm("mov.b64 {%0, %1}, %2;" : "=f"(lo), "=f"(hi) : "l"(v));
    return make_float2(lo, hi);
}

// ---------------- prep (stage 1 only): pack x as float4 (x,y,z,|p|^2) ------
__global__ __launch_bounds__(256) void prep_pts_kernel(const float* __restrict__ x, int b0)
{
    int t = blockIdx.x*256 + threadIdx.x;
    if (t >= NB*NN) return;
    size_t pt = (size_t)b0*NN + t;
    const float* src = x + pt*3;
    float px = src[0], py = src[1], pz = src[2];
    g_pts[pt] = make_float4(px, py, pz, px*px + py*py + pz*pz);
}

// ---------------- kNN v7: warp-per-query, enc-domain + redux inserts -------
__global__ __launch_bounds__(256) void knn_kernel(int b0)
{
    __shared__ float4 pts[NN];
    int tid = threadIdx.x;
    int b = b0 + blockIdx.x;
    for (int j = tid; j < NN; j += 256)
        pts[j] = g_pts[(size_t)b*NN + j];
    __syncthreads();

    int w = tid >> 5, lane = tid & 31;
    int i = blockIdx.y*8 + w;
    float4 q = pts[i];
    float qx2 = 2.f*q.x, qy2 = 2.f*q.y, qz2 = 2.f*q.z, qw = q.w;

    unsigned be  = (lane < KNN) ? ENC_NEGINF : 0xFFFFFFFFu;
    int      bi  = 0;
    unsigned thr = ENC_NEGINF;

    for (int ch = 0; ch < NN/64; ch++){
        int j0 = ch*64 + lane;
        float4 p0 = pts[j0];
        float4 p1 = pts[j0 + 32];
        float t0 = fmaf(qz2, p0.z, -qw);
        t0 = fmaf(qy2, p0.y, t0);
        t0 = fmaf(qx2, p0.x, t0);
        unsigned e0 = fenc(t0 - p0.w);
        float t1 = fmaf(qz2, p1.z, -qw);
        t1 = fmaf(qy2, p1.y, t1);
        t1 = fmaf(qx2, p1.x, t1);
        unsigned e1 = fenc(t1 - p1.w);

        unsigned mask = __ballot_sync(FULLM, e0 > thr);
        while (mask){
            int src = __ffs(mask) - 1;
            mask &= mask - 1;
            unsigned e = __shfl_sync(FULLM, e0, src);
            if (e > thr){
                unsigned mv = __reduce_min_sync(FULLM, be);
                if (e > mv){
                    unsigned own = __ballot_sync(FULLM, be == mv);
                    int ml = __ffs(own) - 1;
                    if (lane == ml){ be = e; bi = j0 - lane + src; }
                }
                thr = mv;
            }
        }
        mask = __ballot_sync(FULLM, e1 > thr);
        while (mask){
            int src = __ffs(mask) - 1;
            mask &= mask - 1;
            unsigned e = __shfl_sync(FULLM, e1, src);
            if (e > thr){
                unsigned mv = __reduce_min_sync(FULLM, be);
                if (e > mv){
                    unsigned own = __ballot_sync(FULLM, be == mv);
                    int ml = __ffs(own) - 1;
                    if (lane == ml){ be = e; bi = j0 - lane + 32 + src; }
                }
                thr = mv;
            }
        }
    }
    if (lane < KNN)
        g_idx[((size_t)b*NN + i)*KNN + lane] = bi;
}

// ---------------- gemmYT v2: Y' = s*(x@Wlo^T), T' = s*(x@Wd^T)+b -----------
template<int C, int SEL>
__global__ __launch_bounds__(256) void gemmYT_kernel(
    const float* __restrict__ x, const float* __restrict__ W,
    const float* __restrict__ bng, const float* __restrict__ bnb,
    const float* __restrict__ bnm, const float* __restrict__ bnv, int b0)
{
    const float* __restrict__ xin = (SEL == 0) ? x : (SEL == 1) ? g_x1 : g_x2;

    __shared__ __align__(16) float Wlo[C*64];
    __shared__ __align__(16) float Wd [C*64];
    __shared__ __align__(16) float xS [32*C];

    int tid = threadIdx.x;
    size_t pt0 = (size_t)b0*NN + blockIdx.x*32;

    for (int t = tid; t < C*64; t += 256){
        int o = t & 63, c = t >> 6;
        float lo = W[(size_t)o*(2*C) + c];
        Wlo[c*64 + o] = lo;
        Wd [c*64 + o] = W[(size_t)o*(2*C) + C + c] - lo;
    }
    for (int t = tid; t < 32*C; t += 256){
        int p = t / C, c = t % C;
        xS[p*C + c] = xin[(pt0 + p)*C + c];
    }
    __syncthreads();

    int o0 = (tid & 15)*4;
    int p0 = (tid >> 4)*2, p1 = p0 + 1;

    float aY0[4]={0,0,0,0}, aT0[4]={0,0,0,0};
    float aY1[4]={0,0,0,0}, aT1[4]={0,0,0,0};

#pragma unroll 4
    for (int c = 0; c < C; c++){
        float4 wl = *(const float4*)&Wlo[c*64 + o0];
        float4 wd = *(const float4*)&Wd [c*64 + o0];
        float x0 = xS[p0*C + c];
        float x1 = xS[p1*C + c];
        aY0[0]=fmaf(x0,wl.x,aY0[0]); aY0[1]=fmaf(x0,wl.y,aY0[1]);
        aY0[2]=fmaf(x0,wl.z,aY0[2]); aY0[3]=fmaf(x0,wl.w,aY0[3]);
        aT0[0]=fmaf(x0,wd.x,aT0[0]); aT0[1]=fmaf(x0,wd.y,aT0[1]);
        aT0[2]=fmaf(x0,wd.z,aT0[2]); aT0[3]=fmaf(x0,wd.w,aT0[3]);
        aY1[0]=fmaf(x1,wl.x,aY1[0]); aY1[1]=fmaf(x1,wl.y,aY1[1]);
        aY1[2]=fmaf(x1,wl.z,aY1[2]); aY1[3]=fmaf(x1,wl.w,aY1[3]);
        aT1[0]=fmaf(x1,wd.x,aT1[0]); aT1[1]=fmaf(x1,wd.y,aT1[1]);
        aT1[2]=fmaf(x1,wd.z,aT1[2]); aT1[3]=fmaf(x1,wd.w,aT1[3]);
    }

    float4 gv = *(const float4*)&bng[o0];
    float4 bv = *(const float4*)&bnb[o0];
    float4 mv = *(const float4*)&bnm[o0];
    float4 vv = *(const float4*)&bnv[o0];
    float s[4], bo[4];
    s[0] = gv.x*rsqrtf(vv.x + EPSB); bo[0] = bv.x - mv.x*s[0];
    s[1] = gv.y*rsqrtf(vv.y + EPSB); bo[1] = bv.y - mv.y*s[1];
    s[2] = gv.z*rsqrtf(vv.z + EPSB); bo[2] = bv.z - mv.z*s[2];
    s[3] = gv.w*rsqrtf(vv.w + EPSB); bo[3] = bv.w - mv.w*s[3];

    float4 r;
    r = make_float4(s[0]*aY0[0], s[1]*aY0[1], s[2]*aY0[2], s[3]*aY0[3]);
    *(float4*)&g_Y[(pt0 + p0)*64 + o0] = r;
    r = make_float4(s[0]*aY1[0], s[1]*aY1[1], s[2]*aY1[2], s[3]*aY1[3]);
    *(float4*)&g_Y[(pt0 + p1)*64 + o0] = r;
    r = make_float4(fmaf(s[0],aT0[0],bo[0]), fmaf(s[1],aT0[1],bo[1]),
                    fmaf(s[2],aT0[2],bo[2]), fmaf(s[3],aT0[3],bo[3]));
    *(float4*)&g_T[(pt0 + p0)*64 + o0] = r;
    r = make_float4(fmaf(s[0],aT1[0],bo[0]), fmaf(s[1],aT1[1],bo[1]),
                    fmaf(s[2],aT1[2],bo[2]), fmaf(s[3],aT1[3],bo[3]));
    *(float4*)&g_T[(pt0 + p1)*64 + o0] = r;
}

// ---------------- edge_conv2 v4: 4 points/block, 5x4 tile, high occupancy --
// block 256 = (r5 = tid&15 -> rows 5r5..5r5+4 of 80, og = (tid>>4)*4)
template<int SEL_OUT>
__global__ __launch_bounds__(256) void edge_conv2_kernel(
    const float* __restrict__ Wb,
    const float* __restrict__ bng, const float* __restrict__ bnb,
    const float* __restrict__ bnm, const float* __restrict__ bnv, int b0)
{
    float* __restrict__ xout = (SEL_OUT == 1) ? g_x1 : g_x2;

    __shared__ __align__(16) float Ws[64*64];
    __shared__ __align__(16) float As[64*81];    // [c][r], r = 0..79
    __shared__ __align__(16) float red[4*4*64];  // [part][p][o]
    __shared__ int idxS[80];

    int tid = threadIdx.x;
    size_t pt0 = (size_t)b0*NN + blockIdx.x*4;

    for (int t = tid; t < 4096; t += 256){
        int o = t & 63, c = t >> 6;
        Ws[c*64 + o] = Wb[(size_t)o*64 + c];
    }
    if (tid < 80) idxS[tid] = g_idx[pt0*KNN + tid];
    __syncthreads();

    for (int e = tid; e < 80*64; e += 256){
        int r = e >> 6, c = e & 63;
        int p = r / KNN;
        size_t bb = (pt0 + p) >> 11;
        int j = idxS[r];
        float v = g_Y[(bb*NN + j)*64 + c] + g_T[(pt0 + p)*64 + c];
        As[c*81 + r] = lrelu(v);
    }

    int r5 = tid & 15;
    int og = (tid >> 4) * 4;

    float s2[4], b2[4];
#pragma unroll
    for (int q = 0; q < 4; q++){
        int o = og + q;
        float r = rsqrtf(bnv[o] + EPSB);
        s2[q] = bng[o]*r; b2[q] = bnb[o] - bnm[o]*s2[q];
    }
    __syncthreads();

    float acc[5][4];
#pragma unroll
    for (int i = 0; i < 5; i++)
#pragma unroll
        for (int q = 0; q < 4; q++) acc[i][q] = 0.f;

#pragma unroll 4
    for (int c = 0; c < 64; c++){
        float4 wA = *(const float4*)&Ws[c*64 + og];
        float a[5];
#pragma unroll
        for (int i = 0; i < 5; i++) a[i] = As[c*81 + r5*5 + i];
#pragma unroll
        for (int i = 0; i < 5; i++){
            acc[i][0]=fmaf(a[i],wA.x,acc[i][0]); acc[i][1]=fmaf(a[i],wA.y,acc[i][1]);
            acc[i][2]=fmaf(a[i],wA.z,acc[i][2]); acc[i][3]=fmaf(a[i],wA.w,acc[i][3]);
        }
    }

    int p    = r5 >> 2;      // point 0..3
    int part = r5 & 3;
#pragma unroll
    for (int q = 0; q < 4; q++){
        float mx = -CUDART_INF_F;
#pragma unroll
        for (int i = 0; i < 5; i++)
            mx = fmaxf(mx, lrelu(fmaf(acc[i][q], s2[q], b2[q])));
        red[(part*4 + p)*64 + og + q] = mx;
    }
    __syncthreads();

    {   // 256 threads = 4 points x 64 channels
        int pp = tid >> 6, oo = tid & 63;
        float m = red[(0*4 + pp)*64 + oo];
        m = fmaxf(m, red[(1*4 + pp)*64 + oo]);
        m = fmaxf(m, red[(2*4 + pp)*64 + oo]);
        m = fmaxf(m, red[(3*4 + pp)*64 + oo]);
        xout[(pt0 + pp)*64 + oo] = m;
        // fused prep for next stage's kNN (channels 6..8)
        if (oo == 0){
            float v0 = fmaxf(fmaxf(red[(0*4+pp)*64+6], red[(1*4+pp)*64+6]),
                             fmaxf(red[(2*4+pp)*64+6], red[(3*4+pp)*64+6]));
            float v1 = fmaxf(fmaxf(red[(0*4+pp)*64+7], red[(1*4+pp)*64+7]),
                             fmaxf(red[(2*4+pp)*64+7], red[(3*4+pp)*64+7]));
            float v2 = fmaxf(fmaxf(red[(0*4+pp)*64+8], red[(1*4+pp)*64+8]),
                             fmaxf(red[(2*4+pp)*64+8], red[(3*4+pp)*64+8]));
            g_pts[pt0 + pp] = make_float4(v0, v1, v2, v0*v0 + v1*v1 + v2*v2);
        }
    }
}

// ---------------- edge_max (stage 3): x3 = max_k lrelu(Y'[j]+T'[i]) --------
__global__ __launch_bounds__(256) void edge_max_kernel(int b0)
{
    __shared__ int idxS[4*KNN];
    int tid = threadIdx.x;
    size_t pt0 = (size_t)b0*NN + blockIdx.x*4;
    if (tid < 4*KNN) idxS[tid] = g_idx[pt0*KNN + tid];
    __syncthreads();

    int p = tid >> 6, o = tid & 63;
    size_t pt = pt0 + p;
    size_t bb = pt >> 11;
    float tv = g_T[pt*64 + o];
    float m = -CUDART_INF_F;
#pragma unroll
    for (int k = 0; k < KNN; k++){
        int j = idxS[p*KNN + k];
        m = fmaxf(m, lrelu(g_Y[(bb*NN + j)*64 + o] + tv));
    }
    g_x3[pt*64 + o] = m;
}

// ---------------- init / final GEMM v3 (FFMA2) / outputs -------------------
__global__ void init_gmax_kernel(int b0){
    int t = b0*1024 + blockIdx.x*256 + threadIdx.x;
    g_gmax[t] = 0u;
}

__global__ __launch_bounds__(256) void final_kernel(
    const float* __restrict__ W6,
    const float* __restrict__ bn6g, const float* __restrict__ bn6b,
    const float* __restrict__ bn6m, const float* __restrict__ bn6v, int b0)
{
    extern __shared__ float dsm[];
    float* Bs = dsm;              // [192*68]
    float* As = dsm + 192*68;     // [192*68]
    __shared__ float ss6[64], sb6[64];
    __shared__ float red[64*16];

    int tid = threadIdx.x;
    int n0 = blockIdx.x*64;
    int bb = b0 + blockIdx.y;
    int mc = blockIdx.z;

    if (tid < 64){
        int o = n0 + tid;
        float r = rsqrtf(bn6v[o] + EPSB);
        ss6[tid] = bn6g[o]*r; sb6[tid] = bn6b[o] - bn6m[o]*ss6[tid];
    }

    for (int ch = 0; ch < 3; ch++)
        for (int t = tid; t < 4096; t += 256){
            int nn = t >> 6, c = t & 63;
            Bs[(ch*64 + c)*68 + nn] = W6[(size_t)(n0+nn)*192 + ch*64 + c];
        }
    __syncthreads();

    int tm = tid & 15, tn = tid >> 4;
    float s6[4], b6[4];
#pragma unroll
    for (int q = 0; q < 4; q++){ s6[q] = ss6[tn*4+q]; b6[q] = sb6[tn*4+q]; }

    float vmax[4] = {-CUDART_INF_F, -CUDART_INF_F, -CUDART_INF_F, -CUDART_INF_F};

    for (int mi = mc*8; mi < mc*8 + 8; mi++){
        size_t m1 = (size_t)bb*NN + mi*64;
        __syncthreads();
        {
            for (int t = tid; t < 4096; t += 256){
                int m = t >> 6, c = t & 63;
                As[(0*64 + c)*68 + m] = g_x1[(m1 + m)*64 + c];
            }
            for (int t = tid; t < 4096; t += 256){
                int m = t >> 6, c = t & 63;
                As[(1*64 + c)*68 + m] = g_x2[(m1 + m)*64 + c];
            }
            for (int t = tid; t < 4096; t += 256){
                int m = t >> 6, c = t & 63;
                As[(2*64 + c)*68 + m] = g_x3[(m1 + m)*64 + c];
            }
        }
        __syncthreads();

        unsigned long long acc2[4][2];
#pragma unroll
        for (int i = 0; i < 4; i++){ acc2[i][0] = 0ULL; acc2[i][1] = 0ULL; }

#pragma unroll 8
        for (int c = 0; c < 192; c++){
            float4 a = *(const float4*)&As[c*68 + tm*4];
            ulonglong2 bp = *(const ulonglong2*)&Bs[c*68 + tn*4];
            unsigned long long a0 = pack2(a.x), a1 = pack2(a.y),
                               a2 = pack2(a.z), a3 = pack2(a.w);
            fma2(acc2[0][0], a0, bp.x); fma2(acc2[0][1], a0, bp.y);
            fma2(acc2[1][0], a1, bp.x); fma2(acc2[1][1], a1, bp.y);
            fma2(acc2[2][0], a2, bp.x); fma2(acc2[2][1], a2, bp.y);
            fma2(acc2[3][0], a3, bp.x); fma2(acc2[3][1], a3, bp.y);
        }
#pragma unroll
        for (int mq = 0; mq < 4; mq++){
            float2 v0 = unpack2(acc2[mq][0]);
            float2 v1 = unpack2(acc2[mq][1]);
            vmax[0] = fmaxf(vmax[0], lrelu(fmaf(v0.x, s6[0], b6[0])));
            vmax[1] = fmaxf(vmax[1], lrelu(fmaf(v0.y, s6[1], b6[1])));
            vmax[2] = fmaxf(vmax[2], lrelu(fmaf(v1.x, s6[2], b6[2])));
            vmax[3] = fmaxf(vmax[3], lrelu(fmaf(v1.y, s6[3], b6[3])));
        }
    }

    __syncthreads();
#pragma unroll
    for (int nq = 0; nq < 4; nq++) red[(tn*4+nq)*16 + tm] = vmax[nq];
    __syncthreads();
    if (tid < 64){
        float mx = -CUDART_INF_F;
#pragma unroll
        for (int t = 0; t < 16; t++) mx = fmaxf(mx, red[tid*16 + t]);
        atomicMax(&g_gmax[bb*1024 + n0 + tid], fencs(mx));
    }
}

__global__ void feat_kernel(float* __restrict__ out, int b0){
    int t = b0*1024 + blockIdx.x*256 + threadIdx.x;
    out[t] = fdec(g_gmax[t]);
}

// ---------------- x4^T via smem transpose ----------------------------------
__global__ __launch_bounds__(256) void x4t_kernel(float* __restrict__ out, int b0)
{
    __shared__ float T[64*65];
    int tid = threadIdx.x;
    int n0 = blockIdx.x*64;
    int bb = b0 + blockIdx.y;
    int ch = blockIdx.z;
    const float* src = (ch == 0) ? g_x1 : (ch == 1) ? g_x2 : g_x3;

    for (int t = tid; t < 4096; t += 256){
        int c = t & 63, n = t >> 6;
        T[c*65 + n] = src[((size_t)bb*NN + n0 + n)*64 + c];
    }
    __syncthreads();
    size_t base = (size_t)BB*1024 + (size_t)bb*192*NN + (size_t)ch*64*NN;
    for (int t = tid; t < 4096; t += 256){
        int n = t & 63, c = t >> 6;
        out[base + (size_t)c*NN + n0 + n] = T[c*65 + n];
    }
}

// ---------------- launch: four independent 2-batch pipelines ---------------
extern "C" void kernel_launch(void* const* d_in, const int* in_sizes, int n_in,
                              void* d_out, int out_size)
{
    const float* x    = (const float*)d_in[0];
    const float* W1   = (const float*)d_in[1];
    const float* W2   = (const float*)d_in[2];
    const float* W3   = (const float*)d_in[3];
    const float* W4   = (const float*)d_in[4];
    const float* W5   = (const float*)d_in[5];
    const float* W6   = (const float*)d_in[6];
    const float* bng  = (const float*)d_in[7];
    const float* bnb  = (const float*)d_in[8];
    const float* bnm  = (const float*)d_in[9];
    const float* bnv  = (const float*)d_in[10];
    const float* bn6g = (const float*)d_in[11];
    const float* bn6b = (const float*)d_in[12];
    const float* bn6m = (const float*)d_in[13];
    const float* bn6v = (const float*)d_in[14];
    float* out = (float*)d_out;

    static cudaStream_t sx[3] = {nullptr, nullptr, nullptr};
    static cudaEvent_t evRoot, evEnd[3];
    if (!sx[0]){
        for (int i = 0; i < 3; i++){
            cudaStreamCreateWithFlags(&sx[i], cudaStreamNonBlocking);
            cudaEventCreateWithFlags(&evEnd[i], cudaEventDisableTiming);
        }
        cudaEventCreateWithFlags(&evRoot, cudaEventDisableTiming);
        cudaFuncSetAttribute(final_kernel,
            cudaFuncAttributeMaxDynamicSharedMemorySize, 2*192*68*4);
    }
    const int FSMEM = 2*192*68*4;
    cudaStream_t st[4] = {(cudaStream_t)0, sx[0], sx[1], sx[2]};

    cudaEventRecord(evRoot, 0);
    for (int i = 1; i < 4; i++) cudaStreamWaitEvent(st[i], evRoot, 0);

    // s0 stage 1 first so capture idx 3 = edge_conv2<1> (occupancy probe)
    prep_pts_kernel<<<NB*NN/256, 256, 0, st[0]>>>(x, 0);                // 0
    knn_kernel<<<dim3(NB, NN/8), 256, 0, st[0]>>>(0);                   // 1
    gemmYT_kernel<3,0><<<NB*NN/32, 256, 0, st[0]>>>(x, W1, bng, bnb, bnm, bnv, 0); // 2
    edge_conv2_kernel<1><<<NB*NN/4, 256, 0, st[0]>>>(W2, bng+64, bnb+64, bnm+64, bnv+64, 0); // 3 <- ncu

    for (int i = 1; i < 4; i++)
        prep_pts_kernel<<<NB*NN/256, 256, 0, st[i]>>>(x, NB*i);
    for (int i = 1; i < 4; i++)
        knn_kernel<<<dim3(NB, NN/8), 256, 0, st[i]>>>(NB*i);
    for (int i = 1; i < 4; i++)
        gemmYT_kernel<3,0><<<NB*NN/32, 256, 0, st[i]>>>(x, W1, bng, bnb, bnm, bnv, NB*i);
    for (int i = 1; i < 4; i++)
        edge_conv2_kernel<1><<<NB*NN/4, 256, 0, st[i]>>>(W2, bng+64, bnb+64, bnm+64, bnv+64, NB*i);

    for (int i = 0; i < 4; i++)
        init_gmax_kernel<<<NB*1024/256, 256, 0, st[i]>>>(NB*i);

    for (int i = 0; i < 4; i++)
        knn_kernel<<<dim3(NB, NN/8), 256, 0, st[i]>>>(NB*i);
    for (int i = 0; i < 4; i++)
        gemmYT_kernel<64,1><<<NB*NN/32, 256, 0, st[i]>>>(x, W3, bng+2*64, bnb+2*64, bnm+2*64, bnv+2*64, NB*i);
    for (int i = 0; i < 4; i++)
        edge_conv2_kernel<2><<<NB*NN/4, 256, 0, st[i]>>>(W4, bng+3*64, bnb+3*64, bnm+3*64, bnv+3*64, NB*i);

    for (int i = 0; i < 4; i++)
        knn_kernel<<<dim3(NB, NN/8), 256, 0, st[i]>>>(NB*i);
    for (int i = 0; i < 4; i++)
        gemmYT_kernel<64,2><<<NB*NN/32, 256, 0, st[i]>>>(x, W5, bng+4*64, bnb+4*64, bnm+4*64, bnv+4*64, NB*i);
    for (int i = 0; i < 4; i++)
        edge_max_kernel<<<NB*NN/4, 256, 0, st[i]>>>(NB*i);

    for (int i = 0; i < 4; i++)
        final_kernel<<<dim3(1024/64, NB, 4), 256, FSMEM, st[i]>>>(W6, bn6g, bn6b, bn6m, bn6v, NB*i);
    for (int i = 0; i < 4; i++)
        x4t_kernel<<<dim3(NN/64, NB, 3), 256, 0, st[i]>>>(out, NB*i);
    for (int i = 0; i < 4; i++)
        feat_kernel<<<NB*1024/256, 256, 0, st[i]>>>(out, NB*i);

    for (int i = 1; i < 4; i++){
        cudaEventRecord(evEnd[i-1], st[i]);
        cudaStreamWaitEvent(0, evEnd[i-1], 0);
    }
}